// round 3
// baseline (speedup 1.0000x reference)
#include <cuda_runtime.h>
#include <cmath>

#define BB 4
#define SS 1024
#define EE 1024
#define HH 16
#define DD 64
#define MROWS (BB*SS)          // 4096
#define EPSF 1e-7f

// ---------------- device scratch (static, no allocation) ----------------
__device__ float g_pq[MROWS*EE];
__device__ float g_pk[MROWS*EE];
__device__ float g_pv[MROWS*EE];
__device__ float g_tv[MROWS*EE];
__device__ float g_zn[3*EE];
__device__ float g_ch[3*EE];
__device__ float g_sh[3*EE];
__device__ float g_lamx[3*MROWS];
__device__ float g_k2[BB*HH*SS];
__device__ float g_lamv[BB*HH*SS];

__device__ __forceinline__ float warp_sum(float v) {
    #pragma unroll
    for (int o = 16; o > 0; o >>= 1) v += __shfl_xor_sync(0xffffffffu, v, o);
    return v;
}
__device__ __forceinline__ float warp_max(float v) {
    #pragma unroll
    for (int o = 16; o > 0; o >>= 1) v = fmaxf(v, __shfl_xor_sync(0xffffffffu, v, o));
    return v;
}
__device__ __forceinline__ float* pbuf(int s) {
    return s == 0 ? g_pq : (s == 1 ? g_pk : g_pv);
}

// ---------------- per-column stats of z: norm, cosh/sinh(2*r) ----------------
__global__ void prep_cols(const float* __restrict__ z, const float* __restrict__ bias, int zi) {
    for (int c = blockIdx.x * blockDim.x + threadIdx.x; c < EE; c += gridDim.x * blockDim.x) {
        float ss = 0.f;
        for (int r = 0; r < EE; r++) {
            float t = z[(size_t)r * EE + c];
            ss = fmaf(t, t, ss);
        }
        float zn = fmaxf(sqrtf(ss), 1e-15f);
        float tcr = 2.f * bias[c];
        float e = expf(tcr), ei = 1.f / e;
        g_zn[zi*EE + c] = zn;
        g_ch[zi*EE + c] = 0.5f * (e + ei);
        g_sh[zi*EE + c] = 0.5f * (e - ei);
    }
}

// ---------------- per-row conformal factor lam(x) ----------------
__global__ void prep_rows(const float* __restrict__ x, int li) {
    int gw = (blockIdx.x * blockDim.x + threadIdx.x) >> 5;
    int lane = threadIdx.x & 31;
    if (gw >= MROWS) return;
    const float4* row = (const float4*)(x + (size_t)gw * EE);
    float ss = 0.f;
    #pragma unroll
    for (int i = 0; i < 8; i++) {
        float4 v = row[lane + 32*i];
        ss += v.x*v.x + v.y*v.y + v.z*v.z + v.w*v.w;
    }
    ss = warp_sum(ss);
    if (lane == 0) g_lamx[li*MROWS + gw] = 2.f / fmaxf(1.f - ss, EPSF);
}

// ---------------- hlinear GEMM + transcendental epilogue ----------------
#define BM 64
#define BN 64
#define BK 16
__global__ void __launch_bounds__(256) hlinear_gemm(const float* __restrict__ x,
                                                    const float* __restrict__ z, int sel) {
    __shared__ float As[BK][BM + 4];
    __shared__ float Bs[BK][BN];
    float* out = pbuf(sel);
    const float* lamx = g_lamx + sel * MROWS;
    const float* znp  = g_zn + sel * EE;
    const float* chp  = g_ch + sel * EE;
    const float* shp  = g_sh + sel * EE;

    int tid = threadIdx.x;
    int tx = tid & 15, ty = tid >> 4;
    int row0 = blockIdx.y * BM, col0 = blockIdx.x * BN;

    int ar = tid >> 2;
    int ac = (tid & 3) * 4;
    int br = tid >> 4;
    int bc = (tid & 15) * 4;

    float acc[4][4];
    #pragma unroll
    for (int i = 0; i < 4; i++)
        #pragma unroll
        for (int j = 0; j < 4; j++) acc[i][j] = 0.f;

    for (int k0 = 0; k0 < EE; k0 += BK) {
        float4 av = *(const float4*)(x + (size_t)(row0 + ar) * EE + k0 + ac);
        As[ac+0][ar] = av.x; As[ac+1][ar] = av.y; As[ac+2][ar] = av.z; As[ac+3][ar] = av.w;
        *(float4*)&Bs[br][bc] = *(const float4*)(z + (size_t)(k0 + br) * EE + col0 + bc);
        __syncthreads();
        #pragma unroll
        for (int kk = 0; kk < BK; kk++) {
            float a[4], b[4];
            #pragma unroll
            for (int i = 0; i < 4; i++) a[i] = As[kk][ty*4 + i];
            #pragma unroll
            for (int j = 0; j < 4; j++) b[j] = Bs[kk][tx*4 + j];
            #pragma unroll
            for (int i = 0; i < 4; i++)
                #pragma unroll
                for (int j = 0; j < 4; j++) acc[i][j] = fmaf(a[i], b[j], acc[i][j]);
        }
        __syncthreads();
    }

    #pragma unroll
    for (int i = 0; i < 4; i++) {
        int r = row0 + ty*4 + i;
        float lam = lamx[r];
        #pragma unroll
        for (int j = 0; j < 4; j++) {
            int c = col0 + tx*4 + j;
            float zn = znp[c];
            float a = lam * acc[i][j] / zn * chp[c] - (lam - 1.f) * shp[c];
            float vv = 2.f * zn * asinhf(a);
            out[(size_t)r * EE + c] = sinhf(vv);
        }
    }
}

// ---------------- row normalize: w -> Poincare point ----------------
__global__ void row_norm(int sel) {
    float* p = pbuf(sel);
    int gw = (blockIdx.x * blockDim.x + threadIdx.x) >> 5;
    int lane = threadIdx.x & 31;
    if (gw >= MROWS) return;
    float4* row = (float4*)(p + (size_t)gw * EE);
    float4 v[8];
    float ss = 0.f;
    #pragma unroll
    for (int i = 0; i < 8; i++) {
        v[i] = row[lane + 32*i];
        ss += v[i].x*v[i].x + v[i].y*v[i].y + v[i].z*v[i].z + v[i].w*v[i].w;
    }
    ss = warp_sum(ss);
    float f = 1.f / (1.f + sqrtf(1.f + ss));
    #pragma unroll
    for (int i = 0; i < 8; i++) {
        v[i].x *= f; v[i].y *= f; v[i].z *= f; v[i].w *= f;
        row[lane + 32*i] = v[i];
    }
}

// ---------------- per-head K norms and V conformal factors ----------------
__global__ void kv_stats() {
    int gw = (blockIdx.x * blockDim.x + threadIdx.x) >> 5;   // (bh, s) flat
    int lane = threadIdx.x & 31;
    if (gw >= BB*HH*SS) return;
    int bh = gw / SS, s = gw % SS;
    int b = bh >> 4, h = bh & 15;
    size_t off = (size_t)(b*SS + s) * EE + h * DD;
    const float* kr = g_pk + off;
    float k0 = kr[lane], k1 = kr[lane+32];
    float ssk = warp_sum(k0*k0 + k1*k1);
    const float* vr = g_pv + off;
    float v0 = vr[lane], v1 = vr[lane+32];
    float ssv = warp_sum(v0*v0 + v1*v1);
    if (lane == 0) {
        g_k2[gw]   = ssk;
        g_lamv[gw] = 2.f / fmaxf(1.f - ssv, EPSF);
    }
}

// ---------------- attention: warp per query, streaming over keys ----------------
__global__ void __launch_bounds__(256) attention_kernel(float scale_cat) {
    __shared__ float qs[8][64];
    __shared__ float Ks[64 * 33];     // [d][key] transposed, pitch 33
    __shared__ float Vs[32 * 64];     // [key][d]
    __shared__ float k2s[32], lams[32];

    int lane = threadIdx.x & 31;
    int wq   = threadIdx.x >> 5;                 // 0..7: query slot
    int bh = blockIdx.x;
    int b = bh >> 4, h = bh & 15;
    int s = blockIdx.y * 8 + wq;

    const float* qrow = g_pq + (size_t)(b*SS + s) * EE + h * DD;
    qs[wq][lane]      = qrow[lane];
    qs[wq][lane + 32] = qrow[lane + 32];
    __syncwarp();
    float q0 = qs[wq][lane], q1 = qs[wq][lane + 32];
    float q2 = warp_sum(q0*q0 + q1*q1);

    float m = -INFINITY, acc0 = 0.f, acc1 = 0.f, aden = 0.f;

    const float* kbase = g_pk + (size_t)b * SS * EE + h * DD;
    const float* vbase = g_pv + (size_t)b * SS * EE + h * DD;

    for (int kt = 0; kt < SS; kt += 32) {
        // cooperative loads
        for (int i = threadIdx.x; i < 32*64; i += 256) {
            int r = i >> 6, c = i & 63;
            Ks[c*33 + r] = kbase[(size_t)(kt + r) * EE + c];
        }
        for (int i = threadIdx.x; i < 32*16; i += 256) {
            int r = i >> 4, c = i & 15;
            ((float4*)Vs)[r*16 + c] = ((const float4*)(vbase + (size_t)(kt + r) * EE))[c];
        }
        if (threadIdx.x < 32) {
            k2s[threadIdx.x]  = g_k2[bh*SS + kt + threadIdx.x];
            lams[threadIdx.x] = g_lamv[bh*SS + kt + threadIdx.x];
        }
        __syncthreads();

        // lane = local key
        float qk = 0.f;
        #pragma unroll
        for (int d = 0; d < 64; d++) qk = fmaf(qs[wq][d], Ks[d*33 + lane], qk);

        float k2v = k2s[lane], lamk = lams[lane];
        float diff2 = fmaxf(q2 + k2v - 2.f*qk, 0.f);
        float den   = fmaxf((1.f - q2) * (1.f - k2v), EPSF);
        float arg   = fmaxf(1.f + 2.f * diff2 / den, 1.f + 1e-6f);
        float sc_   = -logf(arg + sqrtf(arg*arg - 1.f));   // -dist

        float cm = warp_max(sc_);
        float nm = fmaxf(m, cm);
        float rs = expf(m - nm);
        acc0 *= rs; acc1 *= rs; aden *= rs;
        m = nm;

        float p  = expf(sc_ - m);
        float pl = p * lamk;
        float pd = p * (lamk - 1.f);
        aden += warp_sum(pd);

        #pragma unroll
        for (int j = 0; j < 32; j++) {
            float plb = __shfl_sync(0xffffffffu, pl, j);
            acc0 = fmaf(plb, Vs[j*64 + lane],      acc0);
            acc1 = fmaf(plb, Vs[j*64 + lane + 32], acc1);
        }
        __syncthreads();
    }

    float ad = fmaxf(aden, EPSF);
    float u0 = acc0 / ad, u1 = acc1 / ad;
    float usq = warp_sum(u0*u0 + u1*u1);
    float t = 1.f / (1.f + sqrtf(fmaxf(1.f - usq, EPSF)));
    float m0 = u0 * t, m1 = u1 * t;
    float msq = usq * t * t;
    float n = sqrtf(fmaxf(msq, 1e-15f));
    float tc = fminf(n, 1.f - 1e-6f);
    float ath = 0.5f * logf((1.f + tc) / (1.f - tc));
    float f = ath / n * scale_cat;

    size_t off = (size_t)(b*SS + s) * EE + h * DD;
    g_tv[off + lane]      = m0 * f;
    g_tv[off + lane + 32] = m1 * f;
}

// ---------------- final expmap0 over full E rows ----------------
__global__ void expmap_out(float* __restrict__ out) {
    int row = blockIdx.x;
    const float4* tv = (const float4*)(g_tv + (size_t)row * EE);
    __shared__ float red[8];
    __shared__ float stot;
    float4 v = tv[threadIdx.x];
    float ss = v.x*v.x + v.y*v.y + v.z*v.z + v.w*v.w;
    ss = warp_sum(ss);
    int lane = threadIdx.x & 31, wid = threadIdx.x >> 5;
    if (lane == 0) red[wid] = ss;
    __syncthreads();
    if (threadIdx.x == 0) {
        float t = 0.f;
        #pragma unroll
        for (int i = 0; i < 8; i++) t += red[i];
        stot = t;
    }
    __syncthreads();
    float n = sqrtf(fmaxf(stot, 1e-15f));
    float f = tanhf(n) / n;
    v.x *= f; v.y *= f; v.z *= f; v.w *= f;
    ((float4*)out)[(size_t)row * 256 + threadIdx.x] = v;
}

// ---------------- launch ----------------
extern "C" void kernel_launch(void* const* d_in, const int* in_sizes, int n_in,
                              void* d_out, int out_size) {
    const float* q  = (const float*)d_in[0];
    const float* k  = (const float*)d_in[1];
    const float* v  = (const float*)d_in[2];
    const float* zq = (const float*)d_in[3];
    const float* bq = (const float*)d_in[4];
    const float* zk = (const float*)d_in[5];
    const float* bk = (const float*)d_in[6];
    const float* zv = (const float*)d_in[7];
    const float* bv = (const float*)d_in[8];
    float* out = (float*)d_out;

    // beta-concatenation scale: B(E/2,1/2)/B(D/2,1/2)
    double b1 = lgamma(EE/2.0) + lgamma(0.5) - lgamma(EE/2.0 + 0.5);
    double b2 = lgamma(DD/2.0) + lgamma(0.5) - lgamma(DD/2.0 + 0.5);
    float scale_cat = (float)exp(b1 - b2);

    prep_cols<<<4, 256>>>(zq, bq, 0);
    prep_cols<<<4, 256>>>(zk, bk, 1);
    prep_cols<<<4, 256>>>(zv, bv, 2);

    prep_rows<<<MROWS/8, 256>>>(q, 0);
    prep_rows<<<MROWS/8, 256>>>(k, 1);
    prep_rows<<<MROWS/8, 256>>>(v, 2);

    dim3 gg(EE/BN, MROWS/BM);
    hlinear_gemm<<<gg, 256>>>(q, zq, 0);
    hlinear_gemm<<<gg, 256>>>(k, zk, 1);
    hlinear_gemm<<<gg, 256>>>(v, zv, 2);

    row_norm<<<MROWS/8, 256>>>(0);
    row_norm<<<MROWS/8, 256>>>(1);
    row_norm<<<MROWS/8, 256>>>(2);

    kv_stats<<<(BB*HH*SS)/8, 256>>>();

    dim3 ga(BB*HH, SS/8);
    attention_kernel<<<ga, 256>>>(scale_cat);

    expmap_out<<<MROWS, 256>>>(out);
}

// round 4
// speedup vs baseline: 1.1260x; 1.1260x over previous
#include <cuda_runtime.h>
#include <cmath>

#define BB 4
#define SS 1024
#define EE 1024
#define HH 16
#define DD 64
#define MROWS (BB*SS)          // 4096
#define EPSF 1e-7f

// ---------------- device scratch (static, no allocation) ----------------
__device__ float g_pq[MROWS*EE];
__device__ float g_pk[MROWS*EE];
__device__ float g_pv[MROWS*EE];
__device__ float g_tv[MROWS*EE];
__device__ float g_zn[3*EE];
__device__ float g_ch[3*EE];
__device__ float g_sh[3*EE];
__device__ float g_lamx[3*MROWS];
__device__ float g_k2[BB*HH*SS];
__device__ float g_lamv[BB*HH*SS];

__device__ __forceinline__ float warp_sum(float v) {
    #pragma unroll
    for (int o = 16; o > 0; o >>= 1) v += __shfl_xor_sync(0xffffffffu, v, o);
    return v;
}
__device__ __forceinline__ float warp_min(float v) {
    #pragma unroll
    for (int o = 16; o > 0; o >>= 1) v = fminf(v, __shfl_xor_sync(0xffffffffu, v, o));
    return v;
}
__device__ __forceinline__ float* pbuf(int s) {
    return s == 0 ? g_pq : (s == 1 ? g_pk : g_pv);
}

// ---------------- fused prep: z-column stats + x-row conformal factors ----------------
// blocks [0,12): column stats (3 inputs x 4 blocks of 256 cols)
// blocks [12,1548): row stats (3 inputs x 512 blocks x 8 warps)
__global__ void prep_all(const float* __restrict__ q, const float* __restrict__ k,
                         const float* __restrict__ v,
                         const float* __restrict__ zq, const float* __restrict__ bq,
                         const float* __restrict__ zk, const float* __restrict__ bk,
                         const float* __restrict__ zv, const float* __restrict__ bv) {
    if (blockIdx.x < 12) {
        int zi = blockIdx.x >> 2;
        const float* z    = zi == 0 ? zq : (zi == 1 ? zk : zv);
        const float* bias = zi == 0 ? bq : (zi == 1 ? bk : bv);
        int c = (blockIdx.x & 3) * 256 + threadIdx.x;
        float s0 = 0.f, s1 = 0.f, s2 = 0.f, s3 = 0.f;
        #pragma unroll 1
        for (int r = 0; r < EE; r += 4) {
            float t0 = z[(size_t)(r+0) * EE + c];
            float t1 = z[(size_t)(r+1) * EE + c];
            float t2 = z[(size_t)(r+2) * EE + c];
            float t3 = z[(size_t)(r+3) * EE + c];
            s0 = fmaf(t0, t0, s0); s1 = fmaf(t1, t1, s1);
            s2 = fmaf(t2, t2, s2); s3 = fmaf(t3, t3, s3);
        }
        float ss = (s0 + s1) + (s2 + s3);
        float zn = fmaxf(sqrtf(ss), 1e-15f);
        float tcr = 2.f * bias[c];
        float e = expf(tcr), ei = 1.f / e;
        g_zn[zi*EE + c] = zn;
        g_ch[zi*EE + c] = 0.5f * (e + ei);
        g_sh[zi*EE + c] = 0.5f * (e - ei);
    } else {
        int idx = blockIdx.x - 12;
        int li = idx / 512;
        const float* x = li == 0 ? q : (li == 1 ? k : v);
        int gw = (idx % 512) * 8 + (threadIdx.x >> 5);
        int lane = threadIdx.x & 31;
        const float4* row = (const float4*)(x + (size_t)gw * EE);
        float ss = 0.f;
        #pragma unroll
        for (int i = 0; i < 8; i++) {
            float4 t = row[lane + 32*i];
            ss += t.x*t.x + t.y*t.y + t.z*t.z + t.w*t.w;
        }
        ss = warp_sum(ss);
        if (lane == 0) g_lamx[li*MROWS + gw] = 2.f / fmaxf(1.f - ss, EPSF);
    }
}

// ---------------- hlinear GEMM (128x128x8, 8x8 microtile) + transcendental epilogue ----------------
#define GBM 128
#define GBN 128
#define GBK 8
__global__ void __launch_bounds__(256, 2) hlinear_gemm(const float* __restrict__ x,
                                                       const float* __restrict__ z, int sel) {
    __shared__ float As[2][GBK][GBM + 4];
    __shared__ float Bs[2][GBK][GBN];
    float* out = pbuf(sel);
    const float* lamx = g_lamx + sel * MROWS;
    const float* znp  = g_zn + sel * EE;
    const float* chp  = g_ch + sel * EE;
    const float* shp  = g_sh + sel * EE;

    int tid = threadIdx.x;
    int row0 = blockIdx.y * GBM, col0 = blockIdx.x * GBN;
    int ar = tid >> 1,  ac = (tid & 1) * 4;    // A tile loader: 128 rows x 8 k
    int br = tid >> 5,  bc = (tid & 31) * 4;   // B tile loader: 8 k x 128 cols
    int rx = tid & 15,  ry = tid >> 4;         // compute quadrant mapping

    const float* xa = x + (size_t)(row0 + ar) * EE + ac;
    const float* zb = z + (size_t)br * EE + col0 + bc;

    float4 av = *(const float4*)xa;
    float4 bv = *(const float4*)zb;
    As[0][ac+0][ar] = av.x; As[0][ac+1][ar] = av.y;
    As[0][ac+2][ar] = av.z; As[0][ac+3][ar] = av.w;
    *(float4*)&Bs[0][br][bc] = bv;
    __syncthreads();

    float acc[8][8];
    #pragma unroll
    for (int i = 0; i < 8; i++)
        #pragma unroll
        for (int j = 0; j < 8; j++) acc[i][j] = 0.f;

    int buf = 0;
    for (int k0 = 0; k0 < EE; k0 += GBK) {
        bool more = (k0 + GBK) < EE;
        if (more) {
            av = *(const float4*)(xa + k0 + GBK);
            bv = *(const float4*)(zb + (size_t)(k0 + GBK) * EE);
        }
        #pragma unroll
        for (int kk = 0; kk < GBK; kk++) {
            float4 a0 = *(const float4*)&As[buf][kk][ry*4];
            float4 a1 = *(const float4*)&As[buf][kk][ry*4 + 64];
            float4 b0 = *(const float4*)&Bs[buf][kk][rx*4];
            float4 b1 = *(const float4*)&Bs[buf][kk][rx*4 + 64];
            float a[8] = {a0.x,a0.y,a0.z,a0.w, a1.x,a1.y,a1.z,a1.w};
            float b[8] = {b0.x,b0.y,b0.z,b0.w, b1.x,b1.y,b1.z,b1.w};
            #pragma unroll
            for (int i = 0; i < 8; i++)
                #pragma unroll
                for (int j = 0; j < 8; j++) acc[i][j] = fmaf(a[i], b[j], acc[i][j]);
        }
        if (more) {
            buf ^= 1;
            As[buf][ac+0][ar] = av.x; As[buf][ac+1][ar] = av.y;
            As[buf][ac+2][ar] = av.z; As[buf][ac+3][ar] = av.w;
            *(float4*)&Bs[buf][br][bc] = bv;
            __syncthreads();
        }
    }

    // epilogue: hlinear transcendentals, vectorized stores
    #pragma unroll
    for (int i = 0; i < 8; i++) {
        int r = row0 + ry*4 + ((i < 4) ? i : (i - 4 + 64));
        float lam = lamx[r];
        float lm1 = lam - 1.f;
        #pragma unroll
        for (int jg = 0; jg < 2; jg++) {
            int cb = col0 + rx*4 + jg*64;
            float4 o;
            #pragma unroll
            for (int j = 0; j < 4; j++) {
                int c = cb + j;
                float zn = znp[c];
                float a = lam * acc[i][jg*4 + j] / zn * chp[c] - lm1 * shp[c];
                float vv = 2.f * zn * asinhf(a);
                ((float*)&o)[j] = sinhf(vv);
            }
            *(float4*)&out[(size_t)r * EE + cb] = o;
        }
    }
}

// ---------------- fused: row normalize q/k/v + per-head K norms & V conformal ----------------
__global__ void rnkv_fused() {
    int gw = (blockIdx.x * blockDim.x + threadIdx.x) >> 5;   // row 0..MROWS-1
    int lane = threadIdx.x & 31;
    if (gw >= MROWS) return;
    int b = gw >> 10, s = gw & 1023;

    // q: normalize only
    {
        float4* row = (float4*)(g_pq + (size_t)gw * EE);
        float4 t[8]; float ss = 0.f;
        #pragma unroll
        for (int i = 0; i < 8; i++) {
            t[i] = row[lane + 32*i];
            ss += t[i].x*t[i].x + t[i].y*t[i].y + t[i].z*t[i].z + t[i].w*t[i].w;
        }
        ss = warp_sum(ss);
        float f = 1.f / (1.f + sqrtf(1.f + ss));
        #pragma unroll
        for (int i = 0; i < 8; i++) {
            t[i].x *= f; t[i].y *= f; t[i].z *= f; t[i].w *= f;
            row[lane + 32*i] = t[i];
        }
    }
    // k and v: normalize + per-head stats
    #pragma unroll
    for (int sel = 1; sel <= 2; sel++) {
        float4* row = (float4*)((sel == 1 ? g_pk : g_pv) + (size_t)gw * EE);
        float4 t[8]; float sq[8]; float ss = 0.f;
        #pragma unroll
        for (int i = 0; i < 8; i++) {
            t[i] = row[lane + 32*i];
            sq[i] = t[i].x*t[i].x + t[i].y*t[i].y + t[i].z*t[i].z + t[i].w*t[i].w;
            ss += sq[i];
        }
        ss = warp_sum(ss);
        float f = 1.f / (1.f + sqrtf(1.f + ss));
        float f2 = f * f;
        #pragma unroll
        for (int i = 0; i < 8; i++) {
            t[i].x *= f; t[i].y *= f; t[i].z *= f; t[i].w *= f;
            row[lane + 32*i] = t[i];
            // half-warp reduce: head h = 2*i + (lane>=16)
            float hs = sq[i] * f2;
            #pragma unroll
            for (int o = 8; o > 0; o >>= 1) hs += __shfl_xor_sync(0xffffffffu, hs, o);
            if ((lane & 15) == 0) {
                int h = 2*i + (lane >> 4);
                int idx = ((b*HH + h) * SS) + s;
                if (sel == 1) g_k2[idx] = hs;
                else          g_lamv[idx] = 2.f / fmaxf(1.f - hs, EPSF);
            }
        }
    }
}

// ---------------- attention: warp per query, 64-key tiles, w-ratio softmax (no log/exp) ----------------
__global__ void __launch_bounds__(256) attention_kernel(float scale_cat) {
    __shared__ float qs[8][64];
    __shared__ float Ks[64 * 65];     // [d][key], pitch 65
    __shared__ float Vs[64 * 64];     // [key][d]
    __shared__ float k2s[64], lams[64];

    int lane = threadIdx.x & 31;
    int wq   = threadIdx.x >> 5;
    int bh = blockIdx.x;
    int b = bh >> 4, h = bh & 15;
    int s = blockIdx.y * 8 + wq;

    const float* qrow = g_pq + (size_t)(b*SS + s) * EE + h * DD;
    qs[wq][lane]      = qrow[lane];
    qs[wq][lane + 32] = qrow[lane + 32];
    __syncwarp();
    float q0 = qs[wq][lane], q1 = qs[wq][lane + 32];
    float q2 = warp_sum(q0*q0 + q1*q1);
    float omq = 1.f - q2;

    const float* kbase = g_pk + (size_t)b * SS * EE + h * DD;
    const float* vbase = g_pv + (size_t)b * SS * EE + h * DD;

    float M = __int_as_float(0x7f800000);   // +inf: running MIN of w = e^{dist}
    float acc0 = 0.f, acc1 = 0.f, aden = 0.f;

    for (int kt = 0; kt < SS; kt += 64) {
        for (int i = threadIdx.x; i < 64*64; i += 256) {
            int r = i >> 6, c = i & 63;
            Ks[c*65 + r] = kbase[(size_t)(kt + r) * EE + c];
        }
        for (int i = threadIdx.x; i < 64*16; i += 256) {
            int r = i >> 4, c = i & 15;
            ((float4*)Vs)[r*16 + c] = ((const float4*)(vbase + (size_t)(kt + r) * EE))[c];
        }
        if (threadIdx.x < 64) {
            k2s[threadIdx.x]  = g_k2[bh*SS + kt + threadIdx.x];
            lams[threadIdx.x] = g_lamv[bh*SS + kt + threadIdx.x];
        }
        __syncthreads();

        // two keys per lane: lane, lane+32
        float qk0 = 0.f, qk1 = 0.f;
        #pragma unroll 8
        for (int d = 0; d < 64; d++) {
            float qd = qs[wq][d];
            qk0 = fmaf(qd, Ks[d*65 + lane],      qk0);
            qk1 = fmaf(qd, Ks[d*65 + lane + 32], qk1);
        }
        float k20 = k2s[lane],      lam0 = lams[lane];
        float k21 = k2s[lane + 32], lam1 = lams[lane + 32];

        float d20 = fmaxf(q2 + k20 - 2.f*qk0, 0.f);
        float d21 = fmaxf(q2 + k21 - 2.f*qk1, 0.f);
        float de0 = fmaxf(omq * (1.f - k20), EPSF);
        float de1 = fmaxf(omq * (1.f - k21), EPSF);
        float ar0 = fmaxf(1.f + 2.f * d20 / de0, 1.f + 1e-6f);
        float ar1 = fmaxf(1.f + 2.f * d21 / de1, 1.f + 1e-6f);
        float w0 = ar0 + sqrtf(ar0*ar0 - 1.f);   // e^{dist}
        float w1 = ar1 + sqrtf(ar1*ar1 - 1.f);

        float tmin = warp_min(fminf(w0, w1));
        float Mn = fminf(M, tmin);
        float rs = Mn / M;                        // finite/inf = 0 on first tile
        acc0 *= rs; acc1 *= rs; aden *= rs;
        M = Mn;

        float p0 = __fdividef(M, w0), p1 = __fdividef(M, w1);
        float pl0 = p0 * lam0, pl1 = p1 * lam1;
        aden += warp_sum(fmaf(p0, lam0 - 1.f, p1 * (lam1 - 1.f)));

        #pragma unroll
        for (int j = 0; j < 32; j++) {
            float plb = __shfl_sync(0xffffffffu, pl0, j);
            acc0 = fmaf(plb, Vs[j*64 + lane],      acc0);
            acc1 = fmaf(plb, Vs[j*64 + lane + 32], acc1);
        }
        #pragma unroll
        for (int j = 0; j < 32; j++) {
            float plb = __shfl_sync(0xffffffffu, pl1, j);
            acc0 = fmaf(plb, Vs[(j+32)*64 + lane],      acc0);
            acc1 = fmaf(plb, Vs[(j+32)*64 + lane + 32], acc1);
        }
        __syncthreads();
    }

    float ad = fmaxf(aden, EPSF);
    float u0 = acc0 / ad, u1 = acc1 / ad;
    float usq = warp_sum(u0*u0 + u1*u1);
    float t = 1.f / (1.f + sqrtf(fmaxf(1.f - usq, EPSF)));
    float m0 = u0 * t, m1 = u1 * t;
    float msq = usq * t * t;
    float n = sqrtf(fmaxf(msq, 1e-15f));
    float tc = fminf(n, 1.f - 1e-6f);
    float ath = 0.5f * logf((1.f + tc) / (1.f - tc));
    float f = ath / n * scale_cat;

    size_t off = (size_t)(b*SS + s) * EE + h * DD;
    g_tv[off + lane]      = m0 * f;
    g_tv[off + lane + 32] = m1 * f;
}

// ---------------- final expmap0 over full E rows ----------------
__global__ void expmap_out(float* __restrict__ out) {
    int row = blockIdx.x;
    const float4* tv = (const float4*)(g_tv + (size_t)row * EE);
    __shared__ float red[8];
    __shared__ float stot;
    float4 v = tv[threadIdx.x];
    float ss = v.x*v.x + v.y*v.y + v.z*v.z + v.w*v.w;
    ss = warp_sum(ss);
    int lane = threadIdx.x & 31, wid = threadIdx.x >> 5;
    if (lane == 0) red[wid] = ss;
    __syncthreads();
    if (threadIdx.x == 0) {
        float t = 0.f;
        #pragma unroll
        for (int i = 0; i < 8; i++) t += red[i];
        stot = t;
    }
    __syncthreads();
    float n = sqrtf(fmaxf(stot, 1e-15f));
    float f = tanhf(n) / n;
    v.x *= f; v.y *= f; v.z *= f; v.w *= f;
    ((float4*)out)[(size_t)row * 256 + threadIdx.x] = v;
}

// ---------------- launch ----------------
extern "C" void kernel_launch(void* const* d_in, const int* in_sizes, int n_in,
                              void* d_out, int out_size) {
    const float* q  = (const float*)d_in[0];
    const float* k  = (const float*)d_in[1];
    const float* v  = (const float*)d_in[2];
    const float* zq = (const float*)d_in[3];
    const float* bq = (const float*)d_in[4];
    const float* zk = (const float*)d_in[5];
    const float* bk = (const float*)d_in[6];
    const float* zv = (const float*)d_in[7];
    const float* bv = (const float*)d_in[8];
    float* out = (float*)d_out;

    // beta-concatenation scale: B(E/2,1/2)/B(D/2,1/2)
    double b1 = lgamma(EE/2.0) + lgamma(0.5) - lgamma(EE/2.0 + 0.5);
    double b2 = lgamma(DD/2.0) + lgamma(0.5) - lgamma(DD/2.0 + 0.5);
    float scale_cat = (float)exp(b1 - b2);

    prep_all<<<12 + 3*512, 256>>>(q, k, v, zq, bq, zk, bk, zv, bv);   // launch 0

    dim3 gg(EE/GBN, MROWS/GBM);                                       // (8, 32)
    hlinear_gemm<<<gg, 256>>>(q, zq, 0);                              // launch 1
    hlinear_gemm<<<gg, 256>>>(k, zk, 1);                              // launch 2
    hlinear_gemm<<<gg, 256>>>(v, zv, 2);                              // launch 3

    rnkv_fused<<<MROWS/8, 256>>>();                                   // launch 4

    dim3 ga(BB*HH, SS/8);
    attention_kernel<<<ga, 256>>>(scale_cat);                         // launch 5 -> ncu target

    expmap_out<<<MROWS, 256>>>(out);                                  // launch 6
}

// round 6
// speedup vs baseline: 1.9425x; 1.7252x over previous
#include <cuda_runtime.h>
#include <cmath>

#define BB 4
#define SS 1024
#define EE 1024
#define HH 16
#define DD 64
#define MROWS (BB*SS)          // 4096
#define EPSF 1e-7f

// ---------------- device scratch (static, no allocation) ----------------
__device__ float g_pq[MROWS*EE];
__device__ float g_pk[MROWS*EE];
__device__ float g_pv[MROWS*EE];
__device__ float g_tv[MROWS*EE];
__device__ float g_zn[3*EE];
__device__ float g_ch[3*EE];
__device__ float g_sh[3*EE];
__device__ float g_lamx[3*MROWS];
__device__ float g_q2[BB*HH*SS];
__device__ float g_iomq[BB*HH*SS];
__device__ float g_k2[BB*HH*SS];
__device__ float g_ik2[BB*HH*SS];
__device__ float g_lamv[BB*HH*SS];

__device__ __forceinline__ float warp_sum(float v) {
    #pragma unroll
    for (int o = 16; o > 0; o >>= 1) v += __shfl_xor_sync(0xffffffffu, v, o);
    return v;
}
__device__ __forceinline__ float* pbuf(int s) {
    return s == 0 ? g_pq : (s == 1 ? g_pk : g_pv);
}

// ---------------- fused prep: z-column stats + x-row conformal factors ----------------
__global__ void prep_all(const float* __restrict__ q, const float* __restrict__ k,
                         const float* __restrict__ v,
                         const float* __restrict__ zq, const float* __restrict__ bq,
                         const float* __restrict__ zk, const float* __restrict__ bk,
                         const float* __restrict__ zv, const float* __restrict__ bv) {
    if (blockIdx.x < 12) {
        int zi = blockIdx.x >> 2;
        const float* z    = zi == 0 ? zq : (zi == 1 ? zk : zv);
        const float* bias = zi == 0 ? bq : (zi == 1 ? bk : bv);
        int c = (blockIdx.x & 3) * 256 + threadIdx.x;
        float s0 = 0.f, s1 = 0.f, s2 = 0.f, s3 = 0.f;
        #pragma unroll 1
        for (int r = 0; r < EE; r += 4) {
            float t0 = z[(size_t)(r+0) * EE + c];
            float t1 = z[(size_t)(r+1) * EE + c];
            float t2 = z[(size_t)(r+2) * EE + c];
            float t3 = z[(size_t)(r+3) * EE + c];
            s0 = fmaf(t0, t0, s0); s1 = fmaf(t1, t1, s1);
            s2 = fmaf(t2, t2, s2); s3 = fmaf(t3, t3, s3);
        }
        float ss = (s0 + s1) + (s2 + s3);
        float zn = fmaxf(sqrtf(ss), 1e-15f);
        float tcr = 2.f * bias[c];
        float e = expf(tcr), ei = 1.f / e;
        g_zn[zi*EE + c] = zn;
        g_ch[zi*EE + c] = 0.5f * (e + ei);
        g_sh[zi*EE + c] = 0.5f * (e - ei);
    } else {
        int idx = blockIdx.x - 12;
        int li = idx / 512;
        const float* x = li == 0 ? q : (li == 1 ? k : v);
        int gw = (idx % 512) * 8 + (threadIdx.x >> 5);
        int lane = threadIdx.x & 31;
        const float4* row = (const float4*)(x + (size_t)gw * EE);
        float ss = 0.f;
        #pragma unroll
        for (int i = 0; i < 8; i++) {
            float4 t = row[lane + 32*i];
            ss += t.x*t.x + t.y*t.y + t.z*t.z + t.w*t.w;
        }
        ss = warp_sum(ss);
        if (lane == 0) g_lamx[li*MROWS + gw] = 2.f / fmaxf(1.f - ss, EPSF);
    }
}

// ---------------- hlinear GEMM (128x128x8, 8x8 microtile) + transcendental epilogue ----------------
#define GBM 128
#define GBN 128
#define GBK 8
__global__ void __launch_bounds__(256, 2) hlinear_gemm(const float* __restrict__ x,
                                                       const float* __restrict__ z, int sel) {
    __shared__ float As[2][GBK][GBM + 4];
    __shared__ float Bs[2][GBK][GBN];
    float* out = pbuf(sel);
    const float* lamx = g_lamx + sel * MROWS;
    const float* znp  = g_zn + sel * EE;
    const float* chp  = g_ch + sel * EE;
    const float* shp  = g_sh + sel * EE;

    int tid = threadIdx.x;
    int row0 = blockIdx.y * GBM, col0 = blockIdx.x * GBN;
    int ar = tid >> 1,  ac = (tid & 1) * 4;
    int br = tid >> 5,  bc = (tid & 31) * 4;
    int rx = tid & 15,  ry = tid >> 4;

    const float* xa = x + (size_t)(row0 + ar) * EE + ac;
    const float* zb = z + (size_t)br * EE + col0 + bc;

    float4 av = *(const float4*)xa;
    float4 bv = *(const float4*)zb;
    As[0][ac+0][ar] = av.x; As[0][ac+1][ar] = av.y;
    As[0][ac+2][ar] = av.z; As[0][ac+3][ar] = av.w;
    *(float4*)&Bs[0][br][bc] = bv;
    __syncthreads();

    float acc[8][8];
    #pragma unroll
    for (int i = 0; i < 8; i++)
        #pragma unroll
        for (int j = 0; j < 8; j++) acc[i][j] = 0.f;

    int buf = 0;
    for (int k0 = 0; k0 < EE; k0 += GBK) {
        bool more = (k0 + GBK) < EE;
        if (more) {
            av = *(const float4*)(xa + k0 + GBK);
            bv = *(const float4*)(zb + (size_t)(k0 + GBK) * EE);
        }
        #pragma unroll
        for (int kk = 0; kk < GBK; kk++) {
            float4 a0 = *(const float4*)&As[buf][kk][ry*4];
            float4 a1 = *(const float4*)&As[buf][kk][ry*4 + 64];
            float4 b0 = *(const float4*)&Bs[buf][kk][rx*4];
            float4 b1 = *(const float4*)&Bs[buf][kk][rx*4 + 64];
            float a[8] = {a0.x,a0.y,a0.z,a0.w, a1.x,a1.y,a1.z,a1.w};
            float b[8] = {b0.x,b0.y,b0.z,b0.w, b1.x,b1.y,b1.z,b1.w};
            #pragma unroll
            for (int i = 0; i < 8; i++)
                #pragma unroll
                for (int j = 0; j < 8; j++) acc[i][j] = fmaf(a[i], b[j], acc[i][j]);
        }
        if (more) {
            buf ^= 1;
            As[buf][ac+0][ar] = av.x; As[buf][ac+1][ar] = av.y;
            As[buf][ac+2][ar] = av.z; As[buf][ac+3][ar] = av.w;
            *(float4*)&Bs[buf][br][bc] = bv;
            __syncthreads();
        }
    }

    #pragma unroll
    for (int i = 0; i < 8; i++) {
        int r = row0 + ry*4 + ((i < 4) ? i : (i - 4 + 64));
        float lam = lamx[r];
        float lm1 = lam - 1.f;
        #pragma unroll
        for (int jg = 0; jg < 2; jg++) {
            int cb = col0 + rx*4 + jg*64;
            float4 o;
            #pragma unroll
            for (int j = 0; j < 4; j++) {
                int c = cb + j;
                float zn = znp[c];
                float a = lam * acc[i][jg*4 + j] / zn * chp[c] - lm1 * shp[c];
                float vv = 2.f * zn * asinhf(a);
                ((float*)&o)[j] = sinhf(vv);
            }
            *(float4*)&out[(size_t)r * EE + cb] = o;
        }
    }
}

// ---------------- fused: row normalize q/k/v + per-head stats ----------------
__global__ void rnkv_fused() {
    int gw = (blockIdx.x * blockDim.x + threadIdx.x) >> 5;   // row 0..MROWS-1
    int lane = threadIdx.x & 31;
    if (gw >= MROWS) return;
    int b = gw >> 10, s = gw & 1023;

    #pragma unroll
    for (int sel = 0; sel <= 2; sel++) {
        float4* row = (float4*)(pbuf(sel) + (size_t)gw * EE);
        float4 t[8]; float sq[8]; float ss = 0.f;
        #pragma unroll
        for (int i = 0; i < 8; i++) {
            t[i] = row[lane + 32*i];
            sq[i] = t[i].x*t[i].x + t[i].y*t[i].y + t[i].z*t[i].z + t[i].w*t[i].w;
            ss += sq[i];
        }
        ss = warp_sum(ss);
        float f = 1.f / (1.f + sqrtf(1.f + ss));
        float f2 = f * f;
        #pragma unroll
        for (int i = 0; i < 8; i++) {
            t[i].x *= f; t[i].y *= f; t[i].z *= f; t[i].w *= f;
            row[lane + 32*i] = t[i];
            // half-warp reduce: head h = 2*i + (lane>=16)
            float hs = sq[i] * f2;
            #pragma unroll
            for (int o = 8; o > 0; o >>= 1) hs += __shfl_xor_sync(0xffffffffu, hs, o);
            if ((lane & 15) == 0) {
                int h = 2*i + (lane >> 4);
                int idx = ((b*HH + h) * SS) + s;
                if (sel == 0) {
                    g_q2[idx] = hs;
                    g_iomq[idx] = 1.f / fmaxf(1.f - hs, EPSF);
                } else if (sel == 1) {
                    g_k2[idx] = hs;
                    g_ik2[idx] = 1.f / fmaxf(1.f - hs, EPSF);
                } else {
                    g_lamv[idx] = 2.f / fmaxf(1.f - hs, EPSF);
                }
            }
        }
    }
}

// ---------------- attention: 64q x 64k flash tile, two smem GEMMs ----------------
// thread layout: tx=tid&15 (4 keys / 4 dims), ty=tid>>4 (4 queries)
#define QPITCH 68
__global__ void __launch_bounds__(256, 2) attention_kernel(float scale_cat) {
    extern __shared__ float sm[];
    float* Qs = sm;                 // [d][q] pitch 68   (17408 B)
    float* Ks = sm + 4352;          // [d][k] pitch 68   (17408 B)
    float* Vs = sm + 8704;          // [k][d] pitch 64   (16384 B)
    float* Ps = sm + 12800;         // [k][q] pitch 68   (17408 B)

    int tid = threadIdx.x;
    int tx = tid & 15, ty = tid >> 4;
    int bh = blockIdx.x;
    int b = bh >> 4, h = bh & 15;
    int q0 = blockIdx.y * 64;

    const float* qg = g_pq + (size_t)(b*SS) * EE + h*DD;
    const float* kg = g_pk + (size_t)(b*SS) * EE + h*DD;
    const float* vg = g_pv + (size_t)(b*SS) * EE + h*DD;

    // load Q tile transposed into Qs[d][q]
    {
        int r = tid >> 2, cg = tid & 3;
        const float* src = qg + (size_t)(q0 + r) * EE + cg*16;
        #pragma unroll
        for (int u = 0; u < 4; u++) {
            float4 t = *(const float4*)(src + u*4);
            int c = cg*16 + u*4;
            Qs[(c+0)*QPITCH + r] = t.x; Qs[(c+1)*QPITCH + r] = t.y;
            Qs[(c+2)*QPITCH + r] = t.z; Qs[(c+3)*QPITCH + r] = t.w;
        }
    }

    float q2v[4], cq[4], Rm[4], aden[4], O[4][4];
    #pragma unroll
    for (int j = 0; j < 4; j++) {
        int qi = bh*SS + q0 + ty*4 + j;
        q2v[j] = g_q2[qi];
        cq[j]  = 2.f * g_iomq[qi];
        Rm[j] = 0.f; aden[j] = 0.f;
        #pragma unroll
        for (int i = 0; i < 4; i++) O[j][i] = 0.f;
    }

    for (int kt = 0; kt < SS; kt += 64) {
        // load K transposed + V natural
        {
            int r = tid >> 2, cg = tid & 3;
            const float* ksrc = kg + (size_t)(kt + r) * EE + cg*16;
            const float* vsrc = vg + (size_t)(kt + r) * EE + cg*16;
            #pragma unroll
            for (int u = 0; u < 4; u++) {
                float4 t = *(const float4*)(ksrc + u*4);
                int c = cg*16 + u*4;
                Ks[(c+0)*QPITCH + r] = t.x; Ks[(c+1)*QPITCH + r] = t.y;
                Ks[(c+2)*QPITCH + r] = t.z; Ks[(c+3)*QPITCH + r] = t.w;
                *(float4*)&Vs[r*64 + c] = *(const float4*)(vsrc + u*4);
            }
        }
        __syncthreads();

        // QK GEMM: S[j][i], j=query, i=key
        float S[4][4];
        #pragma unroll
        for (int j = 0; j < 4; j++)
            #pragma unroll
            for (int i = 0; i < 4; i++) S[j][i] = 0.f;
        #pragma unroll 8
        for (int d = 0; d < 64; d++) {
            float4 a4 = *(const float4*)&Qs[d*QPITCH + ty*4];
            float4 b4 = *(const float4*)&Ks[d*QPITCH + tx*4];
            float a[4] = {a4.x, a4.y, a4.z, a4.w};
            float bb[4] = {b4.x, b4.y, b4.z, b4.w};
            #pragma unroll
            for (int j = 0; j < 4; j++)
                #pragma unroll
                for (int i = 0; i < 4; i++) S[j][i] = fmaf(a[j], bb[i], S[j][i]);
        }

        // score transform: R = e^{-dist} = 1+x - sqrt(x(x+2)), x = 2*d2/den
        float k2i[4], cki[4], lmi[4];
        #pragma unroll
        for (int i = 0; i < 4; i++) {
            int kk = bh*SS + kt + tx*4 + i;
            k2i[i] = g_k2[kk]; cki[i] = g_ik2[kk]; lmi[i] = g_lamv[kk];
        }
        float R[4][4], rmx[4];
        #pragma unroll
        for (int j = 0; j < 4; j++) {
            rmx[j] = Rm[j];
            #pragma unroll
            for (int i = 0; i < 4; i++) {
                float d2 = fmaxf(q2v[j] + k2i[i] - 2.f*S[j][i], 0.f);
                float x  = fmaxf(d2 * cki[i] * cq[j], 1e-6f);
                float sq = sqrtf(x * (x + 2.f));
                float r  = fmaxf(1.f + x - sq, 0.f);
                R[j][i] = r;
                rmx[j] = fmaxf(rmx[j], r);
            }
        }
        // reduce max over the 16 lanes sharing these queries
        #pragma unroll
        for (int j = 0; j < 4; j++) {
            #pragma unroll
            for (int o = 1; o < 16; o <<= 1)
                rmx[j] = fmaxf(rmx[j], __shfl_xor_sync(0xffffffffu, rmx[j], o));
        }
        // rescale running state
        float inv[4];
        #pragma unroll
        for (int j = 0; j < 4; j++) {
            float rs = (Rm[j] > 0.f) ? (Rm[j] / rmx[j]) : 0.f;
            Rm[j] = rmx[j];
            inv[j] = 1.f / rmx[j];
            aden[j] *= rs;
            #pragma unroll
            for (int i = 0; i < 4; i++) O[j][i] *= rs;
        }
        // probabilities: write P*lam to Ps[k][q]; accumulate denominator
        #pragma unroll
        for (int i = 0; i < 4; i++) {
            float lm = lmi[i], lm1 = lm - 1.f;
            float4 pv4;
            #pragma unroll
            for (int j = 0; j < 4; j++) {
                float p = R[j][i] * inv[j];
                ((float*)&pv4)[j] = p * lm;
                aden[j] = fmaf(p, lm1, aden[j]);
            }
            *(float4*)&Ps[(tx*4 + i)*QPITCH + ty*4] = pv4;
        }
        __syncthreads();

        // PV GEMM: O[j][i] += Ps[k][q_j] * Vs[k][d_i]
        #pragma unroll 8
        for (int k = 0; k < 64; k++) {
            float4 p4 = *(const float4*)&Ps[k*QPITCH + ty*4];
            float4 v4 = *(const float4*)&Vs[k*64 + tx*4];
            float pp[4] = {p4.x, p4.y, p4.z, p4.w};
            float vv[4] = {v4.x, v4.y, v4.z, v4.w};
            #pragma unroll
            for (int j = 0; j < 4; j++)
                #pragma unroll
                for (int i = 0; i < 4; i++) O[j][i] = fmaf(pp[j], vv[i], O[j][i]);
        }
        __syncthreads();
    }

    // epilogue: gyromidpoint + logmap + beta scale
    #pragma unroll
    for (int j = 0; j < 4; j++) {
        float ad = aden[j];
        #pragma unroll
        for (int o = 1; o < 16; o <<= 1) ad += __shfl_xor_sync(0xffffffffu, ad, o);
        ad = fmaxf(ad, EPSF);
        float iad = 1.f / ad;
        float u[4], usq = 0.f;
        #pragma unroll
        for (int i = 0; i < 4; i++) { u[i] = O[j][i] * iad; usq = fmaf(u[i], u[i], usq); }
        #pragma unroll
        for (int o = 1; o < 16; o <<= 1) usq += __shfl_xor_sync(0xffffffffu, usq, o);
        float t = 1.f / (1.f + sqrtf(fmaxf(1.f - usq, EPSF)));
        float msq = usq * t * t;
        float n = sqrtf(fmaxf(msq, 1e-15f));
        float tc = fminf(n, 1.f - 1e-6f);
        float ath = 0.5f * logf((1.f + tc) / (1.f - tc));
        float f = ath / n * scale_cat * t;
        float4 o4;
        #pragma unroll
        for (int i = 0; i < 4; i++) ((float*)&o4)[i] = u[i] * f;
        *(float4*)&g_tv[(size_t)(b*SS + q0 + ty*4 + j) * EE + h*DD + tx*4] = o4;
    }
}

// ---------------- final expmap0 over full E rows ----------------
__global__ void expmap_out(float* __restrict__ out) {
    int row = blockIdx.x;
    const float4* tv = (const float4*)(g_tv + (size_t)row * EE);
    __shared__ float red[8];
    __shared__ float stot;
    float4 v = tv[threadIdx.x];
    float ss = v.x*v.x + v.y*v.y + v.z*v.z + v.w*v.w;
    ss = warp_sum(ss);
    int lane = threadIdx.x & 31, wid = threadIdx.x >> 5;
    if (lane == 0) red[wid] = ss;
    __syncthreads();
    if (threadIdx.x == 0) {
        float t = 0.f;
        #pragma unroll
        for (int i = 0; i < 8; i++) t += red[i];
        stot = t;
    }
    __syncthreads();
    float n = sqrtf(fmaxf(stot, 1e-15f));
    float f = tanhf(n) / n;
    v.x *= f; v.y *= f; v.z *= f; v.w *= f;
    ((float4*)out)[(size_t)row * 256 + threadIdx.x] = v;
}

// ---------------- launch ----------------
extern "C" void kernel_launch(void* const* d_in, const int* in_sizes, int n_in,
                              void* d_out, int out_size) {
    const float* q  = (const float*)d_in[0];
    const float* k  = (const float*)d_in[1];
    const float* v  = (const float*)d_in[2];
    const float* zq = (const float*)d_in[3];
    const float* bq = (const float*)d_in[4];
    const float* zk = (const float*)d_in[5];
    const float* bk = (const float*)d_in[6];
    const float* zv = (const float*)d_in[7];
    const float* bv = (const float*)d_in[8];
    float* out = (float*)d_out;

    double b1 = lgamma(EE/2.0) + lgamma(0.5) - lgamma(EE/2.0 + 0.5);
    double b2 = lgamma(DD/2.0) + lgamma(0.5) - lgamma(DD/2.0 + 0.5);
    float scale_cat = (float)exp(b1 - b2);

    const int ATT_SMEM = 17152 * 4;   // 68608 bytes
    cudaFuncSetAttribute(attention_kernel, cudaFuncAttributeMaxDynamicSharedMemorySize, ATT_SMEM);

    prep_all<<<12 + 3*512, 256>>>(q, k, v, zq, bq, zk, bk, zv, bv);   // launch 0

    dim3 gg(EE/GBN, MROWS/GBM);
    hlinear_gemm<<<gg, 256>>>(q, zq, 0);                              // launch 1
    hlinear_gemm<<<gg, 256>>>(k, zk, 1);                              // launch 2
    hlinear_gemm<<<gg, 256>>>(v, zv, 2);                              // launch 3

    rnkv_fused<<<MROWS/8, 256>>>();                                   // launch 4

    dim3 ga(BB*HH, SS/64);
    attention_kernel<<<ga, 256, ATT_SMEM>>>(scale_cat);               // launch 5 -> ncu target

    expmap_out<<<MROWS, 256>>>(out);                                  // launch 6
}

// round 9
// speedup vs baseline: 2.0431x; 1.0518x over previous
#include <cuda_runtime.h>
#include <cstdint>
#include <cmath>

#define BB 4
#define SS 1024
#define EE 1024
#define HH 16
#define DD 64
#define MROWS (BB*SS)          // 4096
#define EPSF 1e-7f

// ---------------- device scratch (static, no allocation) ----------------
__device__ float g_pq[MROWS*EE];
__device__ float g_pk[MROWS*EE];
__device__ float g_pv[MROWS*EE];
__device__ float g_tv[MROWS*EE];
__device__ float g_zt[3u*EE*EE];      // transposed weights: zt[n*EE+k] = z[k*EE+n]
__device__ float g_zn[3*EE];
__device__ float g_ch[3*EE];
__device__ float g_sh[3*EE];
__device__ float g_lamx[3*MROWS];
__device__ float g_q2[BB*HH*SS];
__device__ float g_iomq[BB*HH*SS];
__device__ float g_k2[BB*HH*SS];
__device__ float g_ik2[BB*HH*SS];
__device__ float g_lamv[BB*HH*SS];

__device__ __forceinline__ float warp_sum(float v) {
    #pragma unroll
    for (int o = 16; o > 0; o >>= 1) v += __shfl_xor_sync(0xffffffffu, v, o);
    return v;
}
__device__ __forceinline__ float* pbuf(int s) {
    return s == 0 ? g_pq : (s == 1 ? g_pk : g_pv);
}
__device__ __forceinline__ float tf32_hi(float x) {
    float h;
    asm("cvt.rna.tf32.f32 %0, %1;" : "=f"(h) : "f"(x));
    return h;
}
__device__ __forceinline__ void mma8(float* d, const uint32_t* a, const uint32_t* b) {
    asm volatile("mma.sync.aligned.m16n8k8.row.col.f32.tf32.tf32.f32 "
        "{%0,%1,%2,%3}, {%4,%5,%6,%7}, {%8,%9}, {%0,%1,%2,%3};"
        : "+f"(d[0]), "+f"(d[1]), "+f"(d[2]), "+f"(d[3])
        : "r"(a[0]), "r"(a[1]), "r"(a[2]), "r"(a[3]), "r"(b[0]), "r"(b[1]));
}

// ---------------- fused prep: z-column stats + x-row conformal factors + z transpose ----------------
__global__ void prep_all(const float* __restrict__ q, const float* __restrict__ k,
                         const float* __restrict__ v,
                         const float* __restrict__ zq, const float* __restrict__ bq,
                         const float* __restrict__ zk, const float* __restrict__ bk,
                         const float* __restrict__ zv, const float* __restrict__ bv) {
    __shared__ float tsm[32][33];
    if (blockIdx.x < 12) {
        int zi = blockIdx.x >> 2;
        const float* z    = zi == 0 ? zq : (zi == 1 ? zk : zv);
        const float* bias = zi == 0 ? bq : (zi == 1 ? bk : bv);
        int c = (blockIdx.x & 3) * 256 + threadIdx.x;
        float s0 = 0.f, s1 = 0.f, s2 = 0.f, s3 = 0.f;
        #pragma unroll 1
        for (int r = 0; r < EE; r += 4) {
            float t0 = z[(size_t)(r+0) * EE + c];
            float t1 = z[(size_t)(r+1) * EE + c];
            float t2 = z[(size_t)(r+2) * EE + c];
            float t3 = z[(size_t)(r+3) * EE + c];
            s0 = fmaf(t0, t0, s0); s1 = fmaf(t1, t1, s1);
            s2 = fmaf(t2, t2, s2); s3 = fmaf(t3, t3, s3);
        }
        float ss = (s0 + s1) + (s2 + s3);
        float zn = fmaxf(sqrtf(ss), 1e-15f);
        float tcr = 2.f * bias[c];
        float e = expf(tcr), ei = 1.f / e;
        g_zn[zi*EE + c] = zn;
        g_ch[zi*EE + c] = 0.5f * (e + ei);
        g_sh[zi*EE + c] = 0.5f * (e - ei);
    } else if (blockIdx.x < 12 + 3*512) {
        int idx = blockIdx.x - 12;
        int li = idx / 512;
        const float* x = li == 0 ? q : (li == 1 ? k : v);
        int gw = (idx % 512) * 8 + (threadIdx.x >> 5);
        int lane = threadIdx.x & 31;
        const float4* row = (const float4*)(x + (size_t)gw * EE);
        float ss = 0.f;
        #pragma unroll
        for (int i = 0; i < 8; i++) {
            float4 t = row[lane + 32*i];
            ss += t.x*t.x + t.y*t.y + t.z*t.z + t.w*t.w;
        }
        ss = warp_sum(ss);
        if (lane == 0) g_lamx[li*MROWS + gw] = 2.f / fmaxf(1.f - ss, EPSF);
    } else {
        // z transpose: 32x32 tiles
        int idx = blockIdx.x - (12 + 3*512);
        int zi = idx >> 10;
        int t  = idx & 1023;
        int tx = t & 31, ty = t >> 5;
        const float* z = zi == 0 ? zq : (zi == 1 ? zk : zv);
        float* zt = g_zt + (size_t)zi * EE * EE;
        int c = threadIdx.x & 31, r0 = threadIdx.x >> 5;
        #pragma unroll
        for (int i = 0; i < 4; i++) {
            int r = r0 + i*8;
            tsm[r][c] = z[(size_t)(ty*32 + r) * EE + tx*32 + c];
        }
        __syncthreads();
        #pragma unroll
        for (int i = 0; i < 4; i++) {
            int r = r0 + i*8;
            zt[(size_t)(tx*32 + r) * EE + ty*32 + c] = tsm[c][r];
        }
    }
}

// ---------------- 3xTF32 mma.sync hlinear GEMM: 128x128x32 tile ----------------
// smem: k-pair-permuted layout per 8-col group: [c0,c4,c1,c5,c2,c6,c3,c7], pitch 36
#define PIT 36
__global__ void __launch_bounds__(256) hlinear_gemm_tc(const float* __restrict__ x, int sel) {
    __shared__ float As[128 * PIT];
    __shared__ float Bs[128 * PIT];
    float* out = pbuf(sel);
    const float* lamx = g_lamx + sel * MROWS;
    const float* znp  = g_zn + sel * EE;
    const float* chp  = g_ch + sel * EE;
    const float* shp  = g_sh + sel * EE;

    int tid = threadIdx.x;
    int wid = tid >> 5, lane = tid & 31;
    int wm = wid & 1, wn = wid >> 1;            // warp tile: rows wm*64, cols wn*32
    int row0 = blockIdx.y * 128, col0 = blockIdx.x * 128;

    const float* xa = x + (size_t)row0 * EE;
    const float* zb = g_zt + (size_t)sel * EE * EE + (size_t)col0 * EE;

    int r1 = tid >> 2, g1 = tid & 3;            // fill cell: (r1,g1) and (r1+64,g1)
    int lr = lane >> 2, lc = lane & 3;

    float acc[4][4][4];
    #pragma unroll
    for (int mt = 0; mt < 4; mt++)
        #pragma unroll
        for (int nt = 0; nt < 4; nt++)
            #pragma unroll
            for (int i = 0; i < 4; i++) acc[mt][nt][i] = 0.f;

    for (int c = 0; c < 32; c++) {
        if (c) __syncthreads();
        // fill A and B chunks (each 128 rows x 32 k-cols), pair-permuted
        {
            const float* s = xa + (size_t)c * 32 + g1 * 8;
            float4 f0 = *(const float4*)(s + (size_t)r1 * EE);
            float4 f1 = *(const float4*)(s + (size_t)r1 * EE + 4);
            *(float4*)&As[r1*PIT + g1*8]     = make_float4(f0.x, f1.x, f0.y, f1.y);
            *(float4*)&As[r1*PIT + g1*8 + 4] = make_float4(f0.z, f1.z, f0.w, f1.w);
            f0 = *(const float4*)(s + (size_t)(r1+64) * EE);
            f1 = *(const float4*)(s + (size_t)(r1+64) * EE + 4);
            *(float4*)&As[(r1+64)*PIT + g1*8]     = make_float4(f0.x, f1.x, f0.y, f1.y);
            *(float4*)&As[(r1+64)*PIT + g1*8 + 4] = make_float4(f0.z, f1.z, f0.w, f1.w);

            s = zb + (size_t)c * 32 + g1 * 8;
            f0 = *(const float4*)(s + (size_t)r1 * EE);
            f1 = *(const float4*)(s + (size_t)r1 * EE + 4);
            *(float4*)&Bs[r1*PIT + g1*8]     = make_float4(f0.x, f1.x, f0.y, f1.y);
            *(float4*)&Bs[r1*PIT + g1*8 + 4] = make_float4(f0.z, f1.z, f0.w, f1.w);
            f0 = *(const float4*)(s + (size_t)(r1+64) * EE);
            f1 = *(const float4*)(s + (size_t)(r1+64) * EE + 4);
            *(float4*)&Bs[(r1+64)*PIT + g1*8]     = make_float4(f0.x, f1.x, f0.y, f1.y);
            *(float4*)&Bs[(r1+64)*PIT + g1*8 + 4] = make_float4(f0.z, f1.z, f0.w, f1.w);
        }
        __syncthreads();

        #pragma unroll
        for (int ks = 0; ks < 4; ks++) {
            int pb = ks*8 + lc*2;
            uint32_t ah[4][4], al[4][4], bh[4][2], bl[4][2];
            #pragma unroll
            for (int mt = 0; mt < 4; mt++) {
                int r = wm*64 + mt*16 + lr;
                float2 p0 = *(const float2*)&As[r*PIT + pb];
                float2 p1 = *(const float2*)&As[(r+8)*PIT + pb];
                float h;
                h = tf32_hi(p0.x); ah[mt][0] = __float_as_uint(h); al[mt][0] = __float_as_uint(p0.x - h);
                h = tf32_hi(p1.x); ah[mt][1] = __float_as_uint(h); al[mt][1] = __float_as_uint(p1.x - h);
                h = tf32_hi(p0.y); ah[mt][2] = __float_as_uint(h); al[mt][2] = __float_as_uint(p0.y - h);
                h = tf32_hi(p1.y); ah[mt][3] = __float_as_uint(h); al[mt][3] = __float_as_uint(p1.y - h);
            }
            #pragma unroll
            for (int nt = 0; nt < 4; nt++) {
                int n = wn*32 + nt*8 + lr;
                float2 p = *(const float2*)&Bs[n*PIT + pb];
                float h;
                h = tf32_hi(p.x); bh[nt][0] = __float_as_uint(h); bl[nt][0] = __float_as_uint(p.x - h);
                h = tf32_hi(p.y); bh[nt][1] = __float_as_uint(h); bl[nt][1] = __float_as_uint(p.y - h);
            }
            #pragma unroll
            for (int mt = 0; mt < 4; mt++)
                #pragma unroll
                for (int nt = 0; nt < 4; nt++) {
                    mma8(acc[mt][nt], ah[mt], bh[nt]);
                    mma8(acc[mt][nt], al[mt], bh[nt]);
                    mma8(acc[mt][nt], ah[mt], bl[nt]);
                }
        }
    }

    // epilogue: transcendentals + STG.64 pairs
    #pragma unroll
    for (int mt = 0; mt < 4; mt++) {
        int rA = row0 + wm*64 + mt*16 + lr;
        int rB = rA + 8;
        float lamA = lamx[rA], lamB = lamx[rB];
        float lA1 = lamA - 1.f, lB1 = lamB - 1.f;
        #pragma unroll
        for (int nt = 0; nt < 4; nt++) {
            int cc = col0 + wn*32 + nt*8 + lc*2;
            float zn0 = znp[cc], zn1 = znp[cc+1];
            float ch0 = chp[cc], ch1 = chp[cc+1];
            float sh0 = shp[cc], sh1 = shp[cc+1];
            float a00 = lamA * acc[mt][nt][0] / zn0 * ch0 - lA1 * sh0;
            float a01 = lamA * acc[mt][nt][1] / zn1 * ch1 - lA1 * sh1;
            float a10 = lamB * acc[mt][nt][2] / zn0 * ch0 - lB1 * sh0;
            float a11 = lamB * acc[mt][nt][3] / zn1 * ch1 - lB1 * sh1;
            float2 oA = make_float2(sinhf(2.f*zn0*asinhf(a00)), sinhf(2.f*zn1*asinhf(a01)));
            float2 oB = make_float2(sinhf(2.f*zn0*asinhf(a10)), sinhf(2.f*zn1*asinhf(a11)));
            *(float2*)&out[(size_t)rA * EE + cc] = oA;
            *(float2*)&out[(size_t)rB * EE + cc] = oB;
        }
    }
}

// ---------------- fused: row normalize q/k/v + per-head stats ----------------
__global__ void rnkv_fused() {
    int gw = (blockIdx.x * blockDim.x + threadIdx.x) >> 5;
    int lane = threadIdx.x & 31;
    if (gw >= MROWS) return;
    int b = gw >> 10, s = gw & 1023;

    #pragma unroll
    for (int sel = 0; sel <= 2; sel++) {
        float4* row = (float4*)(pbuf(sel) + (size_t)gw * EE);
        float4 t[8]; float sq[8]; float ss = 0.f;
        #pragma unroll
        for (int i = 0; i < 8; i++) {
            t[i] = row[lane + 32*i];
            sq[i] = t[i].x*t[i].x + t[i].y*t[i].y + t[i].z*t[i].z + t[i].w*t[i].w;
            ss += sq[i];
        }
        ss = warp_sum(ss);
        float f = 1.f / (1.f + sqrtf(1.f + ss));
        float f2 = f * f;
        #pragma unroll
        for (int i = 0; i < 8; i++) {
            t[i].x *= f; t[i].y *= f; t[i].z *= f; t[i].w *= f;
            row[lane + 32*i] = t[i];
            float hs = sq[i] * f2;
            #pragma unroll
            for (int o = 8; o > 0; o >>= 1) hs += __shfl_xor_sync(0xffffffffu, hs, o);
            if ((lane & 15) == 0) {
                int h = 2*i + (lane >> 4);
                int idx = ((b*HH + h) * SS) + s;
                if (sel == 0) {
                    g_q2[idx] = hs;
                    g_iomq[idx] = 1.f / fmaxf(1.f - hs, EPSF);
                } else if (sel == 1) {
                    g_k2[idx] = hs;
                    g_ik2[idx] = 1.f / fmaxf(1.f - hs, EPSF);
                } else {
                    g_lamv[idx] = 2.f / fmaxf(1.f - hs, EPSF);
                }
            }
        }
    }
}

// ---------------- attention: 64q x 64k flash tile, two smem GEMMs ----------------
#define QPITCH 68
__global__ void __launch_bounds__(256, 2) attention_kernel(float scale_cat) {
    extern __shared__ float sm[];
    float* Qs = sm;
    float* Ks = sm + 4352;
    float* Vs = sm + 8704;
    float* Ps = sm + 12800;

    int tid = threadIdx.x;
    int tx = tid & 15, ty = tid >> 4;
    int bh = blockIdx.x;
    int b = bh >> 4, h = bh & 15;
    int q0 = blockIdx.y * 64;

    const float* qg = g_pq + (size_t)(b*SS) * EE + h*DD;
    const float* kg = g_pk + (size_t)(b*SS) * EE + h*DD;
    const float* vg = g_pv + (size_t)(b*SS) * EE + h*DD;

    {
        int r = tid >> 2, cg = tid & 3;
        const float* src = qg + (size_t)(q0 + r) * EE + cg*16;
        #pragma unroll
        for (int u = 0; u < 4; u++) {
            float4 t = *(const float4*)(src + u*4);
            int c = cg*16 + u*4;
            Qs[(c+0)*QPITCH + r] = t.x; Qs[(c+1)*QPITCH + r] = t.y;
            Qs[(c+2)*QPITCH + r] = t.z; Qs[(c+3)*QPITCH + r] = t.w;
        }
    }

    float q2v[4], cq[4], Rm[4], aden[4], O[4][4];
    #pragma unroll
    for (int j = 0; j < 4; j++) {
        int qi = bh*SS + q0 + ty*4 + j;
        q2v[j] = g_q2[qi];
        cq[j]  = 2.f * g_iomq[qi];
        Rm[j] = 0.f; aden[j] = 0.f;
        #pragma unroll
        for (int i = 0; i < 4; i++) O[j][i] = 0.f;
    }

    for (int kt = 0; kt < SS; kt += 64) {
        {
            int r = tid >> 2, cg = tid & 3;
            const float* ksrc = kg + (size_t)(kt + r) * EE + cg*16;
            const float* vsrc = vg + (size_t)(kt + r) * EE + cg*16;
            #pragma unroll
            for (int u = 0; u < 4; u++) {
                float4 t = *(const float4*)(ksrc + u*4);
                int c = cg*16 + u*4;
                Ks[(c+0)*QPITCH + r] = t.x; Ks[(c+1)*QPITCH + r] = t.y;
                Ks[(c+2)*QPITCH + r] = t.z; Ks[(c+3)*QPITCH + r] = t.w;
                *(float4*)&Vs[r*64 + c] = *(const float4*)(vsrc + u*4);
            }
        }
        __syncthreads();

        float S[4][4];
        #pragma unroll
        for (int j = 0; j < 4; j++)
            #pragma unroll
            for (int i = 0; i < 4; i++) S[j][i] = 0.f;
        #pragma unroll 8
        for (int d = 0; d < 64; d++) {
            float4 a4 = *(const float4*)&Qs[d*QPITCH + ty*4];
            float4 b4 = *(const float4*)&Ks[d*QPITCH + tx*4];
            float a[4] = {a4.x, a4.y, a4.z, a4.w};
            float bb[4] = {b4.x, b4.y, b4.z, b4.w};
            #pragma unroll
            for (int j = 0; j < 4; j++)
                #pragma unroll
                for (int i = 0; i < 4; i++) S[j][i] = fmaf(a[j], bb[i], S[j][i]);
        }

        float k2i[4], cki[4], lmi[4];
        #pragma unroll
        for (int i = 0; i < 4; i++) {
            int kk = bh*SS + kt + tx*4 + i;
            k2i[i] = g_k2[kk]; cki[i] = g_ik2[kk]; lmi[i] = g_lamv[kk];
        }
        float R[4][4], rmx[4];
        #pragma unroll
        for (int j = 0; j < 4; j++) {
            rmx[j] = Rm[j];
            #pragma unroll
            for (int i = 0; i < 4; i++) {
                float d2 = fmaxf(q2v[j] + k2i[i] - 2.f*S[j][i], 0.f);
                float x  = fmaxf(d2 * cki[i] * cq[j], 1e-6f);
                float sq = sqrtf(x * (x + 2.f));
                float r  = fmaxf(1.f + x - sq, 0.f);
                R[j][i] = r;
                rmx[j] = fmaxf(rmx[j], r);
            }
        }
        #pragma unroll
        for (int j = 0; j < 4; j++) {
            #pragma unroll
            for (int o = 1; o < 16; o <<= 1)
                rmx[j] = fmaxf(rmx[j], __shfl_xor_sync(0xffffffffu, rmx[j], o));
        }
        float inv[4];
        #pragma unroll
        for (int j = 0; j < 4; j++) {
            float rs = (Rm[j] > 0.f) ? (Rm[j] / rmx[j]) : 0.f;
            Rm[j] = rmx[j];
            inv[j] = 1.f / rmx[j];
            aden[j] *= rs;
            #pragma unroll
            for (int i = 0; i < 4; i++) O[j][i] *= rs;
        }
        #pragma unroll
        for (int i = 0; i < 4; i++) {
            float lm = lmi[i], lm1 = lm - 1.f;
            float4 pv4;
            #pragma unroll
            for (int j = 0; j < 4; j++) {
                float p = R[j][i] * inv[j];
                ((float*)&pv4)[j] = p * lm;
                aden[j] = fmaf(p, lm1, aden[j]);
            }
            *(float4*)&Ps[(tx*4 + i)*QPITCH + ty*4] = pv4;
        }
        __syncthreads();

        #pragma unroll 8
        for (int k = 0; k < 64; k++) {
            float4 p4 = *(const float4*)&Ps[k*QPITCH + ty*4];
            float4 v4 = *(const float4*)&Vs[k*64 + tx*4];
            float pp[4] = {p4.x, p4.y, p4.z, p4.w};
            float vv[4] = {v4.x, v4.y, v4.z, v4.w};
            #pragma unroll
            for (int j = 0; j < 4; j++)
                #pragma unroll
                for (int i = 0; i < 4; i++) O[j][i] = fmaf(pp[j], vv[i], O[j][i]);
        }
        __syncthreads();
    }

    #pragma unroll
    for (int j = 0; j < 4; j++) {
        float ad = aden[j];
        #pragma unroll
        for (int o = 1; o < 16; o <<= 1) ad += __shfl_xor_sync(0xffffffffu, ad, o);
        ad = fmaxf(ad, EPSF);
        float iad = 1.f / ad;
        float u[4], usq = 0.f;
        #pragma unroll
        for (int i = 0; i < 4; i++) { u[i] = O[j][i] * iad; usq = fmaf(u[i], u[i], usq); }
        #pragma unroll
        for (int o = 1; o < 16; o <<= 1) usq += __shfl_xor_sync(0xffffffffu, usq, o);
        float t = 1.f / (1.f + sqrtf(fmaxf(1.f - usq, EPSF)));
        float msq = usq * t * t;
        float n = sqrtf(fmaxf(msq, 1e-15f));
        float tc = fminf(n, 1.f - 1e-6f);
        float ath = 0.5f * logf((1.f + tc) / (1.f - tc));
        float f = ath / n * scale_cat * t;
        float4 o4;
        #pragma unroll
        for (int i = 0; i < 4; i++) ((float*)&o4)[i] = u[i] * f;
        *(float4*)&g_tv[(size_t)(b*SS + q0 + ty*4 + j) * EE + h*DD + tx*4] = o4;
    }
}

// ---------------- final expmap0 over full E rows ----------------
__global__ void expmap_out(float* __restrict__ out) {
    int row = blockIdx.x;
    const float4* tv = (const float4*)(g_tv + (size_t)row * EE);
    __shared__ float red[8];
    __shared__ float stot;
    float4 v = tv[threadIdx.x];
    float ss = v.x*v.x + v.y*v.y + v.z*v.z + v.w*v.w;
    ss = warp_sum(ss);
    int lane = threadIdx.x & 31, wid = threadIdx.x >> 5;
    if (lane == 0) red[wid] = ss;
    __syncthreads();
    if (threadIdx.x == 0) {
        float t = 0.f;
        #pragma unroll
        for (int i = 0; i < 8; i++) t += red[i];
        stot = t;
    }
    __syncthreads();
    float n = sqrtf(fmaxf(stot, 1e-15f));
    float f = tanhf(n) / n;
    v.x *= f; v.y *= f; v.z *= f; v.w *= f;
    ((float4*)out)[(size_t)row * 256 + threadIdx.x] = v;
}

// ---------------- launch ----------------
extern "C" void kernel_launch(void* const* d_in, const int* in_sizes, int n_in,
                              void* d_out, int out_size) {
    const float* q  = (const float*)d_in[0];
    const float* k  = (const float*)d_in[1];
    const float* v  = (const float*)d_in[2];
    const float* zq = (const float*)d_in[3];
    const float* bq = (const float*)d_in[4];
    const float* zk = (const float*)d_in[5];
    const float* bk = (const float*)d_in[6];
    const float* zv = (const float*)d_in[7];
    const float* bv = (const float*)d_in[8];
    float* out = (float*)d_out;

    double b1 = lgamma(EE/2.0) + lgamma(0.5) - lgamma(EE/2.0 + 0.5);
    double b2 = lgamma(DD/2.0) + lgamma(0.5) - lgamma(DD/2.0 + 0.5);
    float scale_cat = (float)exp(b1 - b2);

    const int ATT_SMEM = 17152 * 4;   // 68608 bytes
    cudaFuncSetAttribute(attention_kernel, cudaFuncAttributeMaxDynamicSharedMemorySize, ATT_SMEM);

    prep_all<<<12 + 3*512 + 3*1024, 256>>>(q, k, v, zq, bq, zk, bk, zv, bv);  // launch 0

    dim3 gg(EE/128, MROWS/128);                                               // (8, 32)
    hlinear_gemm_tc<<<gg, 256>>>(q, 0);                                       // launch 1
    hlinear_gemm_tc<<<gg, 256>>>(k, 1);                                       // launch 2
    hlinear_gemm_tc<<<gg, 256>>>(v, 2);                                       // launch 3

    rnkv_fused<<<MROWS/8, 256>>>();                                           // launch 4

    dim3 ga(BB*HH, SS/64);
    attention_kernel<<<ga, 256, ATT_SMEM>>>(scale_cat);                       // launch 5 -> ncu target

    expmap_out<<<MROWS, 256>>>(out);                                          // launch 6
}

// round 10
// speedup vs baseline: 2.0666x; 1.0115x over previous
#include <cuda_runtime.h>
#include <cstdint>
#include <cmath>

#define BB 4
#define SS 1024
#define EE 1024
#define HH 16
#define DD 64
#define MROWS (BB*SS)          // 4096
#define EPSF 1e-7f

// ---------------- device scratch (static, no allocation) ----------------
__device__ float g_pq[MROWS*EE];
__device__ float g_pk[MROWS*EE];
__device__ float g_pv[MROWS*EE];
__device__ float g_tv[MROWS*EE];
__device__ float g_zt[3u*EE*EE];      // transposed weights: zt[n*EE+k] = z[k*EE+n]
__device__ float g_zn[3*EE];
__device__ float g_ch[3*EE];          // cosh(2r)/||z||  (pre-divided)
__device__ float g_sh[3*EE];
__device__ float g_lamx[3*MROWS];
__device__ float g_q2[BB*HH*SS];
__device__ float g_iomq[BB*HH*SS];
__device__ float g_k2[BB*HH*SS];
__device__ float g_ik2[BB*HH*SS];
__device__ float g_lamv[BB*HH*SS];

__device__ __forceinline__ float warp_sum(float v) {
    #pragma unroll
    for (int o = 16; o > 0; o >>= 1) v += __shfl_xor_sync(0xffffffffu, v, o);
    return v;
}
__device__ __forceinline__ float* pbuf(int s) {
    return s == 0 ? g_pq : (s == 1 ? g_pk : g_pv);
}
__device__ __forceinline__ float tf32_hi(float x) {
    float h;
    asm("cvt.rna.tf32.f32 %0, %1;" : "=f"(h) : "f"(x));
    return h;
}
__device__ __forceinline__ void mma8(float* d, const uint32_t* a, const uint32_t* b) {
    asm volatile("mma.sync.aligned.m16n8k8.row.col.f32.tf32.tf32.f32 "
        "{%0,%1,%2,%3}, {%4,%5,%6,%7}, {%8,%9}, {%0,%1,%2,%3};"
        : "+f"(d[0]), "+f"(d[1]), "+f"(d[2]), "+f"(d[3])
        : "r"(a[0]), "r"(a[1]), "r"(a[2]), "r"(a[3]), "r"(b[0]), "r"(b[1]));
}

// ---------------- fused prep: z-column stats + x-row conformal factors + z transpose ----------------
__global__ void prep_all(const float* __restrict__ q, const float* __restrict__ k,
                         const float* __restrict__ v,
                         const float* __restrict__ zq, const float* __restrict__ bq,
                         const float* __restrict__ zk, const float* __restrict__ bk,
                         const float* __restrict__ zv, const float* __restrict__ bv) {
    __shared__ float tsm[32][33];
    if (blockIdx.x < 12) {
        int zi = blockIdx.x >> 2;
        const float* z    = zi == 0 ? zq : (zi == 1 ? zk : zv);
        const float* bias = zi == 0 ? bq : (zi == 1 ? bk : bv);
        int c = (blockIdx.x & 3) * 256 + threadIdx.x;
        float s0 = 0.f, s1 = 0.f, s2 = 0.f, s3 = 0.f;
        #pragma unroll 1
        for (int r = 0; r < EE; r += 4) {
            float t0 = z[(size_t)(r+0) * EE + c];
            float t1 = z[(size_t)(r+1) * EE + c];
            float t2 = z[(size_t)(r+2) * EE + c];
            float t3 = z[(size_t)(r+3) * EE + c];
            s0 = fmaf(t0, t0, s0); s1 = fmaf(t1, t1, s1);
            s2 = fmaf(t2, t2, s2); s3 = fmaf(t3, t3, s3);
        }
        float ss = (s0 + s1) + (s2 + s3);
        float zn = fmaxf(sqrtf(ss), 1e-15f);
        float tcr = 2.f * bias[c];
        float e = expf(tcr), ei = 1.f / e;
        g_zn[zi*EE + c] = zn;
        g_ch[zi*EE + c] = 0.5f * (e + ei) / zn;     // pre-divided by ||z||
        g_sh[zi*EE + c] = 0.5f * (e - ei);
    } else if (blockIdx.x < 12 + 3*512) {
        int idx = blockIdx.x - 12;
        int li = idx / 512;
        const float* x = li == 0 ? q : (li == 1 ? k : v);
        int gw = (idx % 512) * 8 + (threadIdx.x >> 5);
        int lane = threadIdx.x & 31;
        const float4* row = (const float4*)(x + (size_t)gw * EE);
        float ss = 0.f;
        #pragma unroll
        for (int i = 0; i < 8; i++) {
            float4 t = row[lane + 32*i];
            ss += t.x*t.x + t.y*t.y + t.z*t.z + t.w*t.w;
        }
        ss = warp_sum(ss);
        if (lane == 0) g_lamx[li*MROWS + gw] = 2.f / fmaxf(1.f - ss, EPSF);
    } else {
        // z transpose: 32x32 tiles
        int idx = blockIdx.x - (12 + 3*512);
        int zi = idx >> 10;
        int t  = idx & 1023;
        int tx = t & 31, ty = t >> 5;
        const float* z = zi == 0 ? zq : (zi == 1 ? zk : zv);
        float* zt = g_zt + (size_t)zi * EE * EE;
        int c = threadIdx.x & 31, r0 = threadIdx.x >> 5;
        #pragma unroll
        for (int i = 0; i < 4; i++) {
            int r = r0 + i*8;
            tsm[r][c] = z[(size_t)(ty*32 + r) * EE + tx*32 + c];
        }
        __syncthreads();
        #pragma unroll
        for (int i = 0; i < 4; i++) {
            int r = r0 + i*8;
            zt[(size_t)(tx*32 + r) * EE + ty*32 + c] = tsm[c][r];
        }
    }
}

// ---------------- 3xTF32 mma.sync hlinear GEMM: 128x128x32 tile, double-buffered + reg prefetch ----------------
// smem: k-pair-permuted layout per 8-col group: [c0,c4,c1,c5,c2,c6,c3,c7], pitch 36
#define PIT 36
#define CHF (128 * PIT)                      // floats per operand chunk (4608)
#define GEMM_SMEM (4 * CHF * 4)              // 2 buffers x (A+B) = 73728 bytes
__global__ void __launch_bounds__(256) hlinear_gemm_tc(const float* __restrict__ x, int sel) {
    extern __shared__ float smg[];
    float* Asm[2] = { smg,           smg + 2*CHF };
    float* Bsm[2] = { smg + CHF,     smg + 3*CHF };
    float* out = pbuf(sel);
    const float* lamx = g_lamx + sel * MROWS;
    const float* znp  = g_zn + sel * EE;
    const float* chp  = g_ch + sel * EE;
    const float* shp  = g_sh + sel * EE;

    int tid = threadIdx.x;
    int wid = tid >> 5, lane = tid & 31;
    int wm = wid & 1, wn = wid >> 1;            // warp tile: rows wm*64, cols wn*32
    int row0 = blockIdx.y * 128, col0 = blockIdx.x * 128;

    int r1 = tid >> 2, g1 = tid & 3;            // fill cell
    int lr = lane >> 2, lc = lane & 3;

    const float* xa = x + (size_t)(row0 + r1) * EE + g1 * 8;
    const float* xb = xa + (size_t)64 * EE;
    const float* za = g_zt + (size_t)sel * EE * EE + (size_t)(col0 + r1) * EE + g1 * 8;
    const float* zb2 = za + (size_t)64 * EE;

    float4 ra0, ra1, ra2, ra3, rb0, rb1, rb2, rb3;

    #define LDGC(c) do { \
        const float* _p = xa + (c) * 32; \
        ra0 = *(const float4*)_p; ra1 = *(const float4*)(_p + 4); \
        _p = xb + (c) * 32; \
        ra2 = *(const float4*)_p; ra3 = *(const float4*)(_p + 4); \
        _p = za + (c) * 32; \
        rb0 = *(const float4*)_p; rb1 = *(const float4*)(_p + 4); \
        _p = zb2 + (c) * 32; \
        rb2 = *(const float4*)_p; rb3 = *(const float4*)(_p + 4); \
    } while (0)

    #define STSC(b) do { \
        float* _A = Asm[b]; \
        *(float4*)&_A[r1*PIT + g1*8]        = make_float4(ra0.x, ra1.x, ra0.y, ra1.y); \
        *(float4*)&_A[r1*PIT + g1*8 + 4]    = make_float4(ra0.z, ra1.z, ra0.w, ra1.w); \
        *(float4*)&_A[(r1+64)*PIT + g1*8]   = make_float4(ra2.x, ra3.x, ra2.y, ra3.y); \
        *(float4*)&_A[(r1+64)*PIT + g1*8+4] = make_float4(ra2.z, ra3.z, ra2.w, ra3.w); \
        float* _B = Bsm[b]; \
        *(float4*)&_B[r1*PIT + g1*8]        = make_float4(rb0.x, rb1.x, rb0.y, rb1.y); \
        *(float4*)&_B[r1*PIT + g1*8 + 4]    = make_float4(rb0.z, rb1.z, rb0.w, rb1.w); \
        *(float4*)&_B[(r1+64)*PIT + g1*8]   = make_float4(rb2.x, rb3.x, rb2.y, rb3.y); \
        *(float4*)&_B[(r1+64)*PIT + g1*8+4] = make_float4(rb2.z, rb3.z, rb2.w, rb3.w); \
    } while (0)

    float acc[4][4][4];
    #pragma unroll
    for (int mt = 0; mt < 4; mt++)
        #pragma unroll
        for (int nt = 0; nt < 4; nt++)
            #pragma unroll
            for (int i = 0; i < 4; i++) acc[mt][nt][i] = 0.f;

    LDGC(0); STSC(0);           // chunk 0 -> buf 0
    LDGC(1);                    // chunk 1 -> regs
    __syncthreads();

    for (int c = 0; c < 32; c++) {
        int buf = c & 1;
        if (c < 31) STSC(buf ^ 1);      // store prefetched chunk c+1
        if (c < 30) LDGC(c + 2);        // prefetch chunk c+2 (hidden by compute)

        const float* As = Asm[buf];
        const float* Bs = Bsm[buf];
        #pragma unroll
        for (int ks = 0; ks < 4; ks++) {
            int pb = ks*8 + lc*2;
            uint32_t ah[4][4], al[4][4], bh[4][2], bl[4][2];
            #pragma unroll
            for (int mt = 0; mt < 4; mt++) {
                int r = wm*64 + mt*16 + lr;
                float2 p0 = *(const float2*)&As[r*PIT + pb];
                float2 p1 = *(const float2*)&As[(r+8)*PIT + pb];
                float h;
                h = tf32_hi(p0.x); ah[mt][0] = __float_as_uint(h); al[mt][0] = __float_as_uint(p0.x - h);
                h = tf32_hi(p1.x); ah[mt][1] = __float_as_uint(h); al[mt][1] = __float_as_uint(p1.x - h);
                h = tf32_hi(p0.y); ah[mt][2] = __float_as_uint(h); al[mt][2] = __float_as_uint(p0.y - h);
                h = tf32_hi(p1.y); ah[mt][3] = __float_as_uint(h); al[mt][3] = __float_as_uint(p1.y - h);
            }
            #pragma unroll
            for (int nt = 0; nt < 4; nt++) {
                int n = wn*32 + nt*8 + lr;
                float2 p = *(const float2*)&Bs[n*PIT + pb];
                float h;
                h = tf32_hi(p.x); bh[nt][0] = __float_as_uint(h); bl[nt][0] = __float_as_uint(p.x - h);
                h = tf32_hi(p.y); bh[nt][1] = __float_as_uint(h); bl[nt][1] = __float_as_uint(p.y - h);
            }
            #pragma unroll
            for (int mt = 0; mt < 4; mt++)
                #pragma unroll
                for (int nt = 0; nt < 4; nt++) {
                    mma8(acc[mt][nt], ah[mt], bh[nt]);
                    mma8(acc[mt][nt], al[mt], bh[nt]);
                    mma8(acc[mt][nt], ah[mt], bl[nt]);
                }
        }
        __syncthreads();
    }

    // epilogue: transcendentals + STG.64 pairs (ch already divided by ||z||)
    #pragma unroll
    for (int mt = 0; mt < 4; mt++) {
        int rA = row0 + wm*64 + mt*16 + lr;
        int rB = rA + 8;
        float lamA = lamx[rA], lamB = lamx[rB];
        float lA1 = lamA - 1.f, lB1 = lamB - 1.f;
        #pragma unroll
        for (int nt = 0; nt < 4; nt++) {
            int cc = col0 + wn*32 + nt*8 + lc*2;
            float zn0 = znp[cc], zn1 = znp[cc+1];
            float ch0 = chp[cc], ch1 = chp[cc+1];
            float sh0 = shp[cc], sh1 = shp[cc+1];
            float a00 = lamA * acc[mt][nt][0] * ch0 - lA1 * sh0;
            float a01 = lamA * acc[mt][nt][1] * ch1 - lA1 * sh1;
            float a10 = lamB * acc[mt][nt][2] * ch0 - lB1 * sh0;
            float a11 = lamB * acc[mt][nt][3] * ch1 - lB1 * sh1;
            float2 oA = make_float2(sinhf(2.f*zn0*asinhf(a00)), sinhf(2.f*zn1*asinhf(a01)));
            float2 oB = make_float2(sinhf(2.f*zn0*asinhf(a10)), sinhf(2.f*zn1*asinhf(a11)));
            *(float2*)&out[(size_t)rA * EE + cc] = oA;
            *(float2*)&out[(size_t)rB * EE + cc] = oB;
        }
    }
    #undef LDGC
    #undef STSC
}

// ---------------- fused: row normalize q/k/v + per-head stats ----------------
__global__ void rnkv_fused() {
    int gw = (blockIdx.x * blockDim.x + threadIdx.x) >> 5;
    int lane = threadIdx.x & 31;
    if (gw >= MROWS) return;
    int b = gw >> 10, s = gw & 1023;

    #pragma unroll
    for (int sel = 0; sel <= 2; sel++) {
        float4* row = (float4*)(pbuf(sel) + (size_t)gw * EE);
        float4 t[8]; float sq[8]; float ss = 0.f;
        #pragma unroll
        for (int i = 0; i < 8; i++) {
            t[i] = row[lane + 32*i];
            sq[i] = t[i].x*t[i].x + t[i].y*t[i].y + t[i].z*t[i].z + t[i].w*t[i].w;
            ss += sq[i];
        }
        ss = warp_sum(ss);
        float f = 1.f / (1.f + sqrtf(1.f + ss));
        float f2 = f * f;
        #pragma unroll
        for (int i = 0; i < 8; i++) {
            t[i].x *= f; t[i].y *= f; t[i].z *= f; t[i].w *= f;
            row[lane + 32*i] = t[i];
            float hs = sq[i] * f2;
            #pragma unroll
            for (int o = 8; o > 0; o >>= 1) hs += __shfl_xor_sync(0xffffffffu, hs, o);
            if ((lane & 15) == 0) {
                int h = 2*i + (lane >> 4);
                int idx = ((b*HH + h) * SS) + s;
                if (sel == 0) {
                    g_q2[idx] = hs;
                    g_iomq[idx] = 1.f / fmaxf(1.f - hs, EPSF);
                } else if (sel == 1) {
                    g_k2[idx] = hs;
                    g_ik2[idx] = 1.f / fmaxf(1.f - hs, EPSF);
                } else {
                    g_lamv[idx] = 2.f / fmaxf(1.f - hs, EPSF);
                }
            }
        }
    }
}

// ---------------- attention: 64q x 64k flash tile, two smem GEMMs ----------------
#define QPITCH 68
__global__ void __launch_bounds__(256, 2) attention_kernel(float scale_cat) {
    extern __shared__ float sm[];
    float* Qs = sm;
    float* Ks = sm + 4352;
    float* Vs = sm + 8704;
    float* Ps = sm + 12800;

    int tid = threadIdx.x;
    int tx = tid & 15, ty = tid >> 4;
    int bh = blockIdx.x;
    int b = bh >> 4, h = bh & 15;
    int q0 = blockIdx.y * 64;

    const float* qg = g_pq + (size_t)(b*SS) * EE + h*DD;
    const float* kg = g_pk + (size_t)(b*SS) * EE + h*DD;
    const float* vg = g_pv + (size_t)(b*SS) * EE + h*DD;

    {
        int r = tid >> 2, cg = tid & 3;
        const float* src = qg + (size_t)(q0 + r) * EE + cg*16;
        #pragma unroll
        for (int u = 0; u < 4; u++) {
            float4 t = *(const float4*)(src + u*4);
            int c = cg*16 + u*4;
            Qs[(c+0)*QPITCH + r] = t.x; Qs[(c+1)*QPITCH + r] = t.y;
            Qs[(c+2)*QPITCH + r] = t.z; Qs[(c+3)*QPITCH + r] = t.w;
        }
    }

    float q2v[4], cq[4], Rm[4], aden[4], O[4][4];
    #pragma unroll
    for (int j = 0; j < 4; j++) {
        int qi = bh*SS + q0 + ty*4 + j;
        q2v[j] = g_q2[qi];
        cq[j]  = 2.f * g_iomq[qi];
        Rm[j] = 0.f; aden[j] = 0.f;
        #pragma unroll
        for (int i = 0; i < 4; i++) O[j][i] = 0.f;
    }

    for (int kt = 0; kt < SS; kt += 64) {
        {
            int r = tid >> 2, cg = tid & 3;
            const float* ksrc = kg + (size_t)(kt + r) * EE + cg*16;
            const float* vsrc = vg + (size_t)(kt + r) * EE + cg*16;
            #pragma unroll
            for (int u = 0; u < 4; u++) {
                float4 t = *(const float4*)(ksrc + u*4);
                int c = cg*16 + u*4;
                Ks[(c+0)*QPITCH + r] = t.x; Ks[(c+1)*QPITCH + r] = t.y;
                Ks[(c+2)*QPITCH + r] = t.z; Ks[(c+3)*QPITCH + r] = t.w;
                *(float4*)&Vs[r*64 + c] = *(const float4*)(vsrc + u*4);
            }
        }
        __syncthreads();

        float S[4][4];
        #pragma unroll
        for (int j = 0; j < 4; j++)
            #pragma unroll
            for (int i = 0; i < 4; i++) S[j][i] = 0.f;
        #pragma unroll 8
        for (int d = 0; d < 64; d++) {
            float4 a4 = *(const float4*)&Qs[d*QPITCH + ty*4];
            float4 b4 = *(const float4*)&Ks[d*QPITCH + tx*4];
            float a[4] = {a4.x, a4.y, a4.z, a4.w};
            float bb[4] = {b4.x, b4.y, b4.z, b4.w};
            #pragma unroll
            for (int j = 0; j < 4; j++)
                #pragma unroll
                for (int i = 0; i < 4; i++) S[j][i] = fmaf(a[j], bb[i], S[j][i]);
        }

        float k2i[4], cki[4], lmi[4];
        #pragma unroll
        for (int i = 0; i < 4; i++) {
            int kk = bh*SS + kt + tx*4 + i;
            k2i[i] = g_k2[kk]; cki[i] = g_ik2[kk]; lmi[i] = g_lamv[kk];
        }
        float R[4][4], rmx[4];
        #pragma unroll
        for (int j = 0; j < 4; j++) {
            rmx[j] = Rm[j];
            #pragma unroll
            for (int i = 0; i < 4; i++) {
                float d2 = fmaxf(q2v[j] + k2i[i] - 2.f*S[j][i], 0.f);
                float x  = fmaxf(d2 * cki[i] * cq[j], 1e-6f);
                float sq = sqrtf(x * (x + 2.f));
                float r  = fmaxf(1.f + x - sq, 0.f);
                R[j][i] = r;
                rmx[j] = fmaxf(rmx[j], r);
            }
        }
        #pragma unroll
        for (int j = 0; j < 4; j++) {
            #pragma unroll
            for (int o = 1; o < 16; o <<= 1)
                rmx[j] = fmaxf(rmx[j], __shfl_xor_sync(0xffffffffu, rmx[j], o));
        }
        float inv[4];
        #pragma unroll
        for (int j = 0; j < 4; j++) {
            float rs = (Rm[j] > 0.f) ? (Rm[j] / rmx[j]) : 0.f;
            Rm[j] = rmx[j];
            inv[j] = 1.f / rmx[j];
            aden[j] *= rs;
            #pragma unroll
            for (int i = 0; i < 4; i++) O[j][i] *= rs;
        }
        #pragma unroll
        for (int i = 0; i < 4; i++) {
            float lm = lmi[i], lm1 = lm - 1.f;
            float4 pv4;
            #pragma unroll
            for (int j = 0; j < 4; j++) {
                float p = R[j][i] * inv[j];
                ((float*)&pv4)[j] = p * lm;
                aden[j] = fmaf(p, lm1, aden[j]);
            }
            *(float4*)&Ps[(tx*4 + i)*QPITCH + ty*4] = pv4;
        }
        __syncthreads();

        #pragma unroll 8
        for (int k = 0; k < 64; k++) {
            float4 p4 = *(const float4*)&Ps[k*QPITCH + ty*4];
            float4 v4 = *(const float4*)&Vs[k*64 + tx*4];
            float pp[4] = {p4.x, p4.y, p4.z, p4.w};
            float vv[4] = {v4.x, v4.y, v4.z, v4.w};
            #pragma unroll
            for (int j = 0; j < 4; j++)
                #pragma unroll
                for (int i = 0; i < 4; i++) O[j][i] = fmaf(pp[j], vv[i], O[j][i]);
        }
        __syncthreads();
    }

    #pragma unroll
    for (int j = 0; j < 4; j++) {
        float ad = aden[j];
        #pragma unroll
        for (int o = 1; o < 16; o <<= 1) ad += __shfl_xor_sync(0xffffffffu, ad, o);
        ad = fmaxf(ad, EPSF);
        float iad = 1.f / ad;
        float u[4], usq = 0.f;
        #pragma unroll
        for (int i = 0; i < 4; i++) { u[i] = O[j][i] * iad; usq = fmaf(u[i], u[i], usq); }
        #pragma unroll
        for (int o = 1; o < 16; o <<= 1) usq += __shfl_xor_sync(0xffffffffu, usq, o);
        float t = 1.f / (1.f + sqrtf(fmaxf(1.f - usq, EPSF)));
        float msq = usq * t * t;
        float n = sqrtf(fmaxf(msq, 1e-15f));
        float tc = fminf(n, 1.f - 1e-6f);
        float ath = 0.5f * logf((1.f + tc) / (1.f - tc));
        float f = ath / n * scale_cat * t;
        float4 o4;
        #pragma unroll
        for (int i = 0; i < 4; i++) ((float*)&o4)[i] = u[i] * f;
        *(float4*)&g_tv[(size_t)(b*SS + q0 + ty*4 + j) * EE + h*DD + tx*4] = o4;
    }
}

// ---------------- final expmap0 over full E rows ----------------
__global__ void expmap_out(float* __restrict__ out) {
    int row = blockIdx.x;
    const float4* tv = (const float4*)(g_tv + (size_t)row * EE);
    __shared__ float red[8];
    __shared__ float stot;
    float4 v = tv[threadIdx.x];
    float ss = v.x*v.x + v.y*v.y + v.z*v.z + v.w*v.w;
    ss = warp_sum(ss);
    int lane = threadIdx.x & 31, wid = threadIdx.x >> 5;
    if (lane == 0) red[wid] = ss;
    __syncthreads();
    if (threadIdx.x == 0) {
        float t = 0.f;
        #pragma unroll
        for (int i = 0; i < 8; i++) t += red[i];
        stot = t;
    }
    __syncthreads();
    float n = sqrtf(fmaxf(stot, 1e-15f));
    float f = tanhf(n) / n;
    v.x *= f; v.y *= f; v.z *= f; v.w *= f;
    ((float4*)out)[(size_t)row * 256 + threadIdx.x] = v;
}

// ---------------- launch ----------------
extern "C" void kernel_launch(void* const* d_in, const int* in_sizes, int n_in,
                              void* d_out, int out_size) {
    const float* q  = (const float*)d_in[0];
    const float* k  = (const float*)d_in[1];
    const float* v  = (const float*)d_in[2];
    const float* zq = (const float*)d_in[3];
    const float* bq = (const float*)d_in[4];
    const float* zk = (const float*)d_in[5];
    const float* bk = (const float*)d_in[6];
    const float* zv = (const float*)d_in[7];
    const float* bv = (const float*)d_in[8];
    float* out = (float*)d_out;

    double b1 = lgamma(EE/2.0) + lgamma(0.5) - lgamma(EE/2.0 + 0.5);
    double b2 = lgamma(DD/2.0) + lgamma(0.5) - lgamma(DD/2.0 + 0.5);
    float scale_cat = (float)exp(b1 - b2);

    const int ATT_SMEM = 17152 * 4;   // 68608 bytes
    cudaFuncSetAttribute(attention_kernel, cudaFuncAttributeMaxDynamicSharedMemorySize, ATT_SMEM);
    cudaFuncSetAttribute(hlinear_gemm_tc,  cudaFuncAttributeMaxDynamicSharedMemorySize, GEMM_SMEM);

    prep_all<<<12 + 3*512 + 3*1024, 256>>>(q, k, v, zq, bq, zk, bk, zv, bv);  // launch 0

    dim3 gg(EE/128, MROWS/128);                                               // (8, 32)
    hlinear_gemm_tc<<<gg, 256, GEMM_SMEM>>>(q, 0);                            // launch 1
    hlinear_gemm_tc<<<gg, 256, GEMM_SMEM>>>(k, 1);                            // launch 2
    hlinear_gemm_tc<<<gg, 256, GEMM_SMEM>>>(v, 2);                            // launch 3

    rnkv_fused<<<MROWS/8, 256>>>();                                           // launch 4

    dim3 ga(BB*HH, SS/64);
    attention_kernel<<<ga, 256, ATT_SMEM>>>(scale_cat);                       // launch 5

    expmap_out<<<MROWS, 256>>>(out);                                          // launch 6
}

// round 11
// speedup vs baseline: 2.5341x; 1.2263x over previous
#include <cuda_runtime.h>
#include <cuda_bf16.h>
#include <cstdint>
#include <cmath>

#define BB 4
#define SS 1024
#define EE 1024
#define HH 16
#define DD 64
#define MROWS (BB*SS)          // 4096
#define EPSF 1e-7f

// ---------------- device scratch (static, no allocation) ----------------
__device__ float g_pq[MROWS*EE];
__device__ float g_pk[MROWS*EE];
__device__ float g_pv[MROWS*EE];
__device__ float g_tv[MROWS*EE];
__device__ __nv_bfloat16 g_xh[3u*MROWS*EE];   // hi-bf16 of inputs q/k/v
__device__ __nv_bfloat16 g_xl[3u*MROWS*EE];   // lo-bf16 residual
__device__ __nv_bfloat16 g_zth[3u*EE*EE];     // hi-bf16 of z^T  [n][k]
__device__ __nv_bfloat16 g_ztl[3u*EE*EE];     // lo-bf16 residual
__device__ float g_zn[3*EE];
__device__ float g_ch[3*EE];          // cosh(2r)/||z||  (pre-divided)
__device__ float g_sh[3*EE];
__device__ float g_lamx[3*MROWS];
__device__ float g_q2[BB*HH*SS];
__device__ float g_iomq[BB*HH*SS];
__device__ float g_k2[BB*HH*SS];
__device__ float g_ik2[BB*HH*SS];
__device__ float g_lamv[BB*HH*SS];

__device__ __forceinline__ float warp_sum(float v) {
    #pragma unroll
    for (int o = 16; o > 0; o >>= 1) v += __shfl_xor_sync(0xffffffffu, v, o);
    return v;
}
__device__ __forceinline__ float* pbuf(int s) {
    return s == 0 ? g_pq : (s == 1 ? g_pk : g_pv);
}
__device__ __forceinline__ void ldm_x4(uint32_t* d, uint32_t addr) {
    asm volatile("ldmatrix.sync.aligned.m8n8.x4.shared.b16 {%0,%1,%2,%3}, [%4];"
        : "=r"(d[0]), "=r"(d[1]), "=r"(d[2]), "=r"(d[3]) : "r"(addr));
}
__device__ __forceinline__ void ldm_x2(uint32_t* d, uint32_t addr) {
    asm volatile("ldmatrix.sync.aligned.m8n8.x2.shared.b16 {%0,%1}, [%2];"
        : "=r"(d[0]), "=r"(d[1]) : "r"(addr));
}
__device__ __forceinline__ void mma16(float* d, const uint32_t* a, const uint32_t* b) {
    asm volatile("mma.sync.aligned.m16n8k16.row.col.f32.bf16.bf16.f32 "
        "{%0,%1,%2,%3}, {%4,%5,%6,%7}, {%8,%9}, {%0,%1,%2,%3};"
        : "+f"(d[0]), "+f"(d[1]), "+f"(d[2]), "+f"(d[3])
        : "r"(a[0]), "r"(a[1]), "r"(a[2]), "r"(a[3]), "r"(b[0]), "r"(b[1]));
}

// ---------------- fused prep: z stats + x row stats + hi/lo bf16 splits + z^T split ----------------
__global__ void prep_all(const float* __restrict__ q, const float* __restrict__ k,
                         const float* __restrict__ v,
                         const float* __restrict__ zq, const float* __restrict__ bq,
                         const float* __restrict__ zk, const float* __restrict__ bk,
                         const float* __restrict__ zv, const float* __restrict__ bv) {
    __shared__ float tsm[32][33];
    if (blockIdx.x < 12) {
        int zi = blockIdx.x >> 2;
        const float* z    = zi == 0 ? zq : (zi == 1 ? zk : zv);
        const float* bias = zi == 0 ? bq : (zi == 1 ? bk : bv);
        int c = (blockIdx.x & 3) * 256 + threadIdx.x;
        float s0 = 0.f, s1 = 0.f, s2 = 0.f, s3 = 0.f;
        #pragma unroll 1
        for (int r = 0; r < EE; r += 4) {
            float t0 = z[(size_t)(r+0) * EE + c];
            float t1 = z[(size_t)(r+1) * EE + c];
            float t2 = z[(size_t)(r+2) * EE + c];
            float t3 = z[(size_t)(r+3) * EE + c];
            s0 = fmaf(t0, t0, s0); s1 = fmaf(t1, t1, s1);
            s2 = fmaf(t2, t2, s2); s3 = fmaf(t3, t3, s3);
        }
        float ss = (s0 + s1) + (s2 + s3);
        float zn = fmaxf(sqrtf(ss), 1e-15f);
        float tcr = 2.f * bias[c];
        float e = expf(tcr), ei = 1.f / e;
        g_zn[zi*EE + c] = zn;
        g_ch[zi*EE + c] = 0.5f * (e + ei) / zn;
        g_sh[zi*EE + c] = 0.5f * (e - ei);
    } else if (blockIdx.x < 12 + 3*512) {
        int idx = blockIdx.x - 12;
        int li = idx / 512;
        const float* x = li == 0 ? q : (li == 1 ? k : v);
        int gw = (idx % 512) * 8 + (threadIdx.x >> 5);
        int lane = threadIdx.x & 31;
        const float4* row = (const float4*)(x + (size_t)gw * EE);
        __nv_bfloat16* xh = g_xh + (size_t)li * MROWS * EE + (size_t)gw * EE;
        __nv_bfloat16* xl = g_xl + (size_t)li * MROWS * EE + (size_t)gw * EE;
        float ss = 0.f;
        #pragma unroll
        for (int i = 0; i < 8; i++) {
            float4 t = row[lane + 32*i];
            ss += t.x*t.x + t.y*t.y + t.z*t.z + t.w*t.w;
            int c0 = (lane + 32*i) * 4;
            __nv_bfloat16 hx = __float2bfloat16(t.x), hy = __float2bfloat16(t.y);
            __nv_bfloat16 hz = __float2bfloat16(t.z), hw = __float2bfloat16(t.w);
            *(__nv_bfloat162*)(xh + c0)     = __nv_bfloat162{hx, hy};
            *(__nv_bfloat162*)(xh + c0 + 2) = __nv_bfloat162{hz, hw};
            __nv_bfloat16 lx = __float2bfloat16(t.x - __bfloat162float(hx));
            __nv_bfloat16 ly = __float2bfloat16(t.y - __bfloat162float(hy));
            __nv_bfloat16 lz = __float2bfloat16(t.z - __bfloat162float(hz));
            __nv_bfloat16 lw = __float2bfloat16(t.w - __bfloat162float(hw));
            *(__nv_bfloat162*)(xl + c0)     = __nv_bfloat162{lx, ly};
            *(__nv_bfloat162*)(xl + c0 + 2) = __nv_bfloat162{lz, lw};
        }
        ss = warp_sum(ss);
        if (lane == 0) g_lamx[li*MROWS + gw] = 2.f / fmaxf(1.f - ss, EPSF);
    } else {
        // z transpose -> bf16 hi/lo, 32x32 tiles
        int idx = blockIdx.x - (12 + 3*512);
        int zi = idx >> 10;
        int t  = idx & 1023;
        int tx = t & 31, ty = t >> 5;
        const float* z = zi == 0 ? zq : (zi == 1 ? zk : zv);
        __nv_bfloat16* zth = g_zth + (size_t)zi * EE * EE;
        __nv_bfloat16* ztl = g_ztl + (size_t)zi * EE * EE;
        int c = threadIdx.x & 31, r0 = threadIdx.x >> 5;
        #pragma unroll
        for (int i = 0; i < 4; i++) {
            int r = r0 + i*8;
            tsm[r][c] = z[(size_t)(ty*32 + r) * EE + tx*32 + c];
        }
        __syncthreads();
        #pragma unroll
        for (int i = 0; i < 4; i++) {
            int r = r0 + i*8;
            float val = tsm[c][r];
            __nv_bfloat16 h = __float2bfloat16(val);
            size_t o = (size_t)(tx*32 + r) * EE + ty*32 + c;
            zth[o] = h;
            ztl[o] = __float2bfloat16(val - __bfloat162float(h));
        }
    }
}

// ---------------- 3xBF16 mma.sync hlinear GEMM: 128x128x32 tile, ldmatrix, pre-split operands ----------------
#define BPIT 40    // bf16 per smem row (80 bytes): conflict-free for ldmatrix & STS
__global__ void __launch_bounds__(256, 2) hlinear_gemm_tc(int sel) {
    __shared__ __nv_bfloat16 AhS[128*BPIT], AlS[128*BPIT], BhS[128*BPIT], BlS[128*BPIT];
    float* out = pbuf(sel);
    const __nv_bfloat16* xh = g_xh + (size_t)sel * MROWS * EE;
    const __nv_bfloat16* xl = g_xl + (size_t)sel * MROWS * EE;
    const __nv_bfloat16* zh = g_zth + (size_t)sel * EE * EE;
    const __nv_bfloat16* zl = g_ztl + (size_t)sel * EE * EE;
    const float* lamx = g_lamx + sel * MROWS;
    const float* znp  = g_zn + sel * EE;
    const float* chp  = g_ch + sel * EE;
    const float* shp  = g_sh + sel * EE;

    int tid = threadIdx.x;
    int wid = tid >> 5, lane = tid & 31;
    int wm = wid & 1, wn = wid >> 1;            // warp tile: rows wm*64, cols wn*32
    int row0 = blockIdx.y * 128, col0 = blockIdx.x * 128;
    int lr = lane >> 2, lc = lane & 3;
    int tq = lane >> 3, lr8 = lane & 7;

    uint32_t ahB = (uint32_t)__cvta_generic_to_shared(AhS);
    uint32_t alB = (uint32_t)__cvta_generic_to_shared(AlS);
    uint32_t bhB = (uint32_t)__cvta_generic_to_shared(BhS);
    uint32_t blB = (uint32_t)__cvta_generic_to_shared(BlS);

    float acc[4][4][4];
    #pragma unroll
    for (int mt = 0; mt < 4; mt++)
        #pragma unroll
        for (int nt = 0; nt < 4; nt++)
            #pragma unroll
            for (int i = 0; i < 4; i++) acc[mt][nt][i] = 0.f;

    for (int c = 0; c < 32; c++) {
        if (c) __syncthreads();
        // fill: 512 int4 per buffer (128 rows x 64B), 2 iters x 256 threads
        #pragma unroll
        for (int i = 0; i < 2; i++) {
            int idx = i*256 + tid;
            int r = idx >> 2, s2 = idx & 3;
            size_t ga = (size_t)(row0 + r) * EE + c*32 + s2*8;
            size_t gb = (size_t)(col0 + r) * EE + c*32 + s2*8;
            uint32_t so = (uint32_t)(r*80 + s2*16);
            *(int4*)((char*)AhS + so) = *(const int4*)(xh + ga);
            *(int4*)((char*)AlS + so) = *(const int4*)(xl + ga);
            *(int4*)((char*)BhS + so) = *(const int4*)(zh + gb);
            *(int4*)((char*)BlS + so) = *(const int4*)(zl + gb);
        }
        __syncthreads();

        #pragma unroll
        for (int ks = 0; ks < 2; ks++) {
            uint32_t ah[4][4], al[4][4], bh[4][2], bl[4][2];
            #pragma unroll
            for (int mt = 0; mt < 4; mt++) {
                uint32_t ao = (uint32_t)((wm*64 + mt*16 + (tq&1)*8 + lr8)*80 + (2*ks + (tq>>1))*16);
                ldm_x4(ah[mt], ahB + ao);
                ldm_x4(al[mt], alB + ao);
            }
            #pragma unroll
            for (int nt = 0; nt < 4; nt++) {
                uint32_t bo = (uint32_t)((wn*32 + nt*8 + lr8)*80 + (2*ks + (tq&1))*16);
                ldm_x2(bh[nt], bhB + bo);
                ldm_x2(bl[nt], blB + bo);
            }
            #pragma unroll
            for (int mt = 0; mt < 4; mt++)
                #pragma unroll
                for (int nt = 0; nt < 4; nt++) {
                    mma16(acc[mt][nt], ah[mt], bh[nt]);
                    mma16(acc[mt][nt], al[mt], bh[nt]);
                    mma16(acc[mt][nt], ah[mt], bl[nt]);
                }
        }
    }

    // epilogue: transcendentals + STG.64 pairs (ch pre-divided by ||z||)
    #pragma unroll
    for (int mt = 0; mt < 4; mt++) {
        int rA = row0 + wm*64 + mt*16 + lr;
        int rB = rA + 8;
        float lamA = lamx[rA], lamB = lamx[rB];
        float lA1 = lamA - 1.f, lB1 = lamB - 1.f;
        #pragma unroll
        for (int nt = 0; nt < 4; nt++) {
            int cc = col0 + wn*32 + nt*8 + lc*2;
            float zn0 = znp[cc], zn1 = znp[cc+1];
            float ch0 = chp[cc], ch1 = chp[cc+1];
            float sh0 = shp[cc], sh1 = shp[cc+1];
            float a00 = lamA * acc[mt][nt][0] * ch0 - lA1 * sh0;
            float a01 = lamA * acc[mt][nt][1] * ch1 - lA1 * sh1;
            float a10 = lamB * acc[mt][nt][2] * ch0 - lB1 * sh0;
            float a11 = lamB * acc[mt][nt][3] * ch1 - lB1 * sh1;
            float2 oA = make_float2(sinhf(2.f*zn0*asinhf(a00)), sinhf(2.f*zn1*asinhf(a01)));
            float2 oB = make_float2(sinhf(2.f*zn0*asinhf(a10)), sinhf(2.f*zn1*asinhf(a11)));
            *(float2*)&out[(size_t)rA * EE + cc] = oA;
            *(float2*)&out[(size_t)rB * EE + cc] = oB;
        }
    }
}

// ---------------- fused: row normalize q/k/v + per-head stats ----------------
__global__ void rnkv_fused() {
    int gw = (blockIdx.x * blockDim.x + threadIdx.x) >> 5;
    int lane = threadIdx.x & 31;
    if (gw >= MROWS) return;
    int b = gw >> 10, s = gw & 1023;

    #pragma unroll
    for (int sel = 0; sel <= 2; sel++) {
        float4* row = (float4*)(pbuf(sel) + (size_t)gw * EE);
        float4 t[8]; float sq[8]; float ss = 0.f;
        #pragma unroll
        for (int i = 0; i < 8; i++) {
            t[i] = row[lane + 32*i];
            sq[i] = t[i].x*t[i].x + t[i].y*t[i].y + t[i].z*t[i].z + t[i].w*t[i].w;
            ss += sq[i];
        }
        ss = warp_sum(ss);
        float f = 1.f / (1.f + sqrtf(1.f + ss));
        float f2 = f * f;
        #pragma unroll
        for (int i = 0; i < 8; i++) {
            t[i].x *= f; t[i].y *= f; t[i].z *= f; t[i].w *= f;
            row[lane + 32*i] = t[i];
            float hs = sq[i] * f2;
            #pragma unroll
            for (int o = 8; o > 0; o >>= 1) hs += __shfl_xor_sync(0xffffffffu, hs, o);
            if ((lane & 15) == 0) {
                int h = 2*i + (lane >> 4);
                int idx = ((b*HH + h) * SS) + s;
                if (sel == 0) {
                    g_q2[idx] = hs;
                    g_iomq[idx] = 1.f / fmaxf(1.f - hs, EPSF);
                } else if (sel == 1) {
                    g_k2[idx] = hs;
                    g_ik2[idx] = 1.f / fmaxf(1.f - hs, EPSF);
                } else {
                    g_lamv[idx] = 2.f / fmaxf(1.f - hs, EPSF);
                }
            }
        }
    }
}

// ---------------- attention: 64q x 64k flash tile, two smem GEMMs ----------------
#define QPITCH 68
__global__ void __launch_bounds__(256, 2) attention_kernel(float scale_cat) {
    extern __shared__ float sm[];
    float* Qs = sm;
    float* Ks = sm + 4352;
    float* Vs = sm + 8704;
    float* Ps = sm + 12800;

    int tid = threadIdx.x;
    int tx = tid & 15, ty = tid >> 4;
    int bh = blockIdx.x;
    int b = bh >> 4, h = bh & 15;
    int q0 = blockIdx.y * 64;

    const float* qg = g_pq + (size_t)(b*SS) * EE + h*DD;
    const float* kg = g_pk + (size_t)(b*SS) * EE + h*DD;
    const float* vg = g_pv + (size_t)(b*SS) * EE + h*DD;

    {
        int r = tid >> 2, cg = tid & 3;
        const float* src = qg + (size_t)(q0 + r) * EE + cg*16;
        #pragma unroll
        for (int u = 0; u < 4; u++) {
            float4 t = *(const float4*)(src + u*4);
            int c = cg*16 + u*4;
            Qs[(c+0)*QPITCH + r] = t.x; Qs[(c+1)*QPITCH + r] = t.y;
            Qs[(c+2)*QPITCH + r] = t.z; Qs[(c+3)*QPITCH + r] = t.w;
        }
    }

    float q2v[4], cq[4], Rm[4], aden[4], O[4][4];
    #pragma unroll
    for (int j = 0; j < 4; j++) {
        int qi = bh*SS + q0 + ty*4 + j;
        q2v[j] = g_q2[qi];
        cq[j]  = 2.f * g_iomq[qi];
        Rm[j] = 0.f; aden[j] = 0.f;
        #pragma unroll
        for (int i = 0; i < 4; i++) O[j][i] = 0.f;
    }

    for (int kt = 0; kt < SS; kt += 64) {
        {
            int r = tid >> 2, cg = tid & 3;
            const float* ksrc = kg + (size_t)(kt + r) * EE + cg*16;
            const float* vsrc = vg + (size_t)(kt + r) * EE + cg*16;
            #pragma unroll
            for (int u = 0; u < 4; u++) {
                float4 t = *(const float4*)(ksrc + u*4);
                int c = cg*16 + u*4;
                Ks[(c+0)*QPITCH + r] = t.x; Ks[(c+1)*QPITCH + r] = t.y;
                Ks[(c+2)*QPITCH + r] = t.z; Ks[(c+3)*QPITCH + r] = t.w;
                *(float4*)&Vs[r*64 + c] = *(const float4*)(vsrc + u*4);
            }
        }
        __syncthreads();

        float S[4][4];
        #pragma unroll
        for (int j = 0; j < 4; j++)
            #pragma unroll
            for (int i = 0; i < 4; i++) S[j][i] = 0.f;
        #pragma unroll 8
        for (int d = 0; d < 64; d++) {
            float4 a4 = *(const float4*)&Qs[d*QPITCH + ty*4];
            float4 b4 = *(const float4*)&Ks[d*QPITCH + tx*4];
            float a[4] = {a4.x, a4.y, a4.z, a4.w};
            float bb[4] = {b4.x, b4.y, b4.z, b4.w};
            #pragma unroll
            for (int j = 0; j < 4; j++)
                #pragma unroll
                for (int i = 0; i < 4; i++) S[j][i] = fmaf(a[j], bb[i], S[j][i]);
        }

        float k2i[4], cki[4], lmi[4];
        #pragma unroll
        for (int i = 0; i < 4; i++) {
            int kk = bh*SS + kt + tx*4 + i;
            k2i[i] = g_k2[kk]; cki[i] = g_ik2[kk]; lmi[i] = g_lamv[kk];
        }
        float R[4][4], rmx[4];
        #pragma unroll
        for (int j = 0; j < 4; j++) {
            rmx[j] = Rm[j];
            #pragma unroll
            for (int i = 0; i < 4; i++) {
                float d2 = fmaxf(q2v[j] + k2i[i] - 2.f*S[j][i], 0.f);
                float x  = fmaxf(d2 * cki[i] * cq[j], 1e-6f);
                float sq = sqrtf(x * (x + 2.f));
                float r  = fmaxf(1.f + x - sq, 0.f);
                R[j][i] = r;
                rmx[j] = fmaxf(rmx[j], r);
            }
        }
        #pragma unroll
        for (int j = 0; j < 4; j++) {
            #pragma unroll
            for (int o = 1; o < 16; o <<= 1)
                rmx[j] = fmaxf(rmx[j], __shfl_xor_sync(0xffffffffu, rmx[j], o));
        }
        float inv[4];
        #pragma unroll
        for (int j = 0; j < 4; j++) {
            float rs = (Rm[j] > 0.f) ? (Rm[j] / rmx[j]) : 0.f;
            Rm[j] = rmx[j];
            inv[j] = 1.f / rmx[j];
            aden[j] *= rs;
            #pragma unroll
            for (int i = 0; i < 4; i++) O[j][i] *= rs;
        }
        #pragma unroll
        for (int i = 0; i < 4; i++) {
            float lm = lmi[i], lm1 = lm - 1.f;
            float4 pv4;
            #pragma unroll
            for (int j = 0; j < 4; j++) {
                float p = R[j][i] * inv[j];
                ((float*)&pv4)[j] = p * lm;
                aden[j] = fmaf(p, lm1, aden[j]);
            }
            *(float4*)&Ps[(tx*4 + i)*QPITCH + ty*4] = pv4;
        }
        __syncthreads();

        #pragma unroll 8
        for (int k = 0; k < 64; k++) {
            float4 p4 = *(const float4*)&Ps[k*QPITCH + ty*4];
            float4 v4 = *(const float4*)&Vs[k*64 + tx*4];
            float pp[4] = {p4.x, p4.y, p4.z, p4.w};
            float vv[4] = {v4.x, v4.y, v4.z, v4.w};
            #pragma unroll
            for (int j = 0; j < 4; j++)
                #pragma unroll
                for (int i = 0; i < 4; i++) O[j][i] = fmaf(pp[j], vv[i], O[j][i]);
        }
        __syncthreads();
    }

    #pragma unroll
    for (int j = 0; j < 4; j++) {
        float ad = aden[j];
        #pragma unroll
        for (int o = 1; o < 16; o <<= 1) ad += __shfl_xor_sync(0xffffffffu, ad, o);
        ad = fmaxf(ad, EPSF);
        float iad = 1.f / ad;
        float u[4], usq = 0.f;
        #pragma unroll
        for (int i = 0; i < 4; i++) { u[i] = O[j][i] * iad; usq = fmaf(u[i], u[i], usq); }
        #pragma unroll
        for (int o = 1; o < 16; o <<= 1) usq += __shfl_xor_sync(0xffffffffu, usq, o);
        float t = 1.f / (1.f + sqrtf(fmaxf(1.f - usq, EPSF)));
        float msq = usq * t * t;
        float n = sqrtf(fmaxf(msq, 1e-15f));
        float tc = fminf(n, 1.f - 1e-6f);
        float ath = 0.5f * logf((1.f + tc) / (1.f - tc));
        float f = ath / n * scale_cat * t;
        float4 o4;
        #pragma unroll
        for (int i = 0; i < 4; i++) ((float*)&o4)[i] = u[i] * f;
        *(float4*)&g_tv[(size_t)(b*SS + q0 + ty*4 + j) * EE + h*DD + tx*4] = o4;
    }
}

// ---------------- final expmap0 over full E rows ----------------
__global__ void expmap_out(float* __restrict__ out) {
    int row = blockIdx.x;
    const float4* tv = (const float4*)(g_tv + (size_t)row * EE);
    __shared__ float red[8];
    __shared__ float stot;
    float4 v = tv[threadIdx.x];
    float ss = v.x*v.x + v.y*v.y + v.z*v.z + v.w*v.w;
    ss = warp_sum(ss);
    int lane = threadIdx.x & 31, wid = threadIdx.x >> 5;
    if (lane == 0) red[wid] = ss;
    __syncthreads();
    if (threadIdx.x == 0) {
        float t = 0.f;
        #pragma unroll
        for (int i = 0; i < 8; i++) t += red[i];
        stot = t;
    }
    __syncthreads();
    float n = sqrtf(fmaxf(stot, 1e-15f));
    float f = tanhf(n) / n;
    v.x *= f; v.y *= f; v.z *= f; v.w *= f;
    ((float4*)out)[(size_t)row * 256 + threadIdx.x] = v;
}

// ---------------- launch ----------------
extern "C" void kernel_launch(void* const* d_in, const int* in_sizes, int n_in,
                              void* d_out, int out_size) {
    const float* q  = (const float*)d_in[0];
    const float* k  = (const float*)d_in[1];
    const float* v  = (const float*)d_in[2];
    const float* zq = (const float*)d_in[3];
    const float* bq = (const float*)d_in[4];
    const float* zk = (const float*)d_in[5];
    const float* bk = (const float*)d_in[6];
    const float* zv = (const float*)d_in[7];
    const float* bv = (const float*)d_in[8];
    float* out = (float*)d_out;

    double b1 = lgamma(EE/2.0) + lgamma(0.5) - lgamma(EE/2.0 + 0.5);
    double b2 = lgamma(DD/2.0) + lgamma(0.5) - lgamma(DD/2.0 + 0.5);
    float scale_cat = (float)exp(b1 - b2);

    const int ATT_SMEM = 17152 * 4;   // 68608 bytes
    cudaFuncSetAttribute(attention_kernel, cudaFuncAttributeMaxDynamicSharedMemorySize, ATT_SMEM);

    prep_all<<<12 + 3*512 + 3*1024, 256>>>(q, k, v, zq, bq, zk, bk, zv, bv);  // launch 0

    dim3 gg(EE/128, MROWS/128);                                               // (8, 32)
    hlinear_gemm_tc<<<gg, 256>>>(0);                                          // launch 1
    hlinear_gemm_tc<<<gg, 256>>>(1);                                          // launch 2
    hlinear_gemm_tc<<<gg, 256>>>(2);                                          // launch 3

    rnkv_fused<<<MROWS/8, 256>>>();                                           // launch 4

    dim3 ga(BB*HH, SS/64);
    attention_kernel<<<ga, 256, ATT_SMEM>>>(scale_cat);                       // launch 5

    expmap_out<<<MROWS, 256>>>(out);                                          // launch 6
}

// round 17
// speedup vs baseline: 3.7458x; 1.4781x over previous
#include <cuda_runtime.h>
#include <cuda_bf16.h>
#include <cstdint>
#include <cmath>

#define BB 4
#define SS 1024
#define EE 1024
#define HH 16
#define DD 64
#define MROWS (BB*SS)          // 4096
#define EPSF 1e-7f

// ---------------- device scratch (static, no allocation) ----------------
__device__ float g_pq[MROWS*EE];
__device__ float g_pk[MROWS*EE];
__device__ float g_pv[MROWS*EE];
__device__ float g_tv[MROWS*EE];
__device__ __nv_bfloat16 g_xh[3u*MROWS*EE];   // hi-bf16: pre-GEMM inputs, then post-rnkv normalized q/k/v
__device__ __nv_bfloat16 g_xl[3u*MROWS*EE];   // lo-bf16 residual
__device__ __nv_bfloat16 g_zth[3u*EE*EE];     // hi-bf16 of z^T  [n][k]
__device__ __nv_bfloat16 g_ztl[3u*EE*EE];     // lo-bf16 residual
__device__ float g_zn[3*EE];
__device__ float g_ch[3*EE];          // cosh(2r)/||z||  (pre-divided)
__device__ float g_sh[3*EE];
__device__ float g_lamx[3*MROWS];
__device__ float g_q2[BB*HH*SS];
__device__ float g_iomq[BB*HH*SS];
__device__ float g_k2[BB*HH*SS];
__device__ float g_ik2[BB*HH*SS];
__device__ float g_lamv[BB*HH*SS];

__device__ __forceinline__ float warp_sum(float v) {
    #pragma unroll
    for (int o = 16; o > 0; o >>= 1) v += __shfl_xor_sync(0xffffffffu, v, o);
    return v;
}
__device__ __forceinline__ float* pbuf(int s) {
    return s == 0 ? g_pq : (s == 1 ? g_pk : g_pv);
}
__device__ __forceinline__ void ldm_x4(uint32_t* d, uint32_t addr) {
    asm volatile("ldmatrix.sync.aligned.m8n8.x4.shared.b16 {%0,%1,%2,%3}, [%4];"
        : "=r"(d[0]), "=r"(d[1]), "=r"(d[2]), "=r"(d[3]) : "r"(addr));
}
__device__ __forceinline__ void ldm_x2(uint32_t* d, uint32_t addr) {
    asm volatile("ldmatrix.sync.aligned.m8n8.x2.shared.b16 {%0,%1}, [%2];"
        : "=r"(d[0]), "=r"(d[1]) : "r"(addr));
}
__device__ __forceinline__ void ldm_x2t(uint32_t* d, uint32_t addr) {
    asm volatile("ldmatrix.sync.aligned.m8n8.x2.trans.shared.b16 {%0,%1}, [%2];"
        : "=r"(d[0]), "=r"(d[1]) : "r"(addr));
}
__device__ __forceinline__ void mma16(float* d, const uint32_t* a, const uint32_t* b) {
    asm volatile("mma.sync.aligned.m16n8k16.row.col.f32.bf16.bf16.f32 "
        "{%0,%1,%2,%3}, {%4,%5,%6,%7}, {%8,%9}, {%0,%1,%2,%3};"
        : "+f"(d[0]), "+f"(d[1]), "+f"(d[2]), "+f"(d[3])
        : "r"(a[0]), "r"(a[1]), "r"(a[2]), "r"(a[3]), "r"(b[0]), "r"(b[1]));
}
__device__ __forceinline__ uint32_t packbf(float lo, float hi) {
    uint32_t r;
    asm("cvt.rn.bf16x2.f32 %0, %1, %2;" : "=r"(r) : "f"(hi), "f"(lo));
    return r;
}
__device__ __forceinline__ float tobf(float x) {
    return __bfloat162float(__float2bfloat16(x));
}

// ---------------- fused prep: z stats + x row stats + hi/lo bf16 splits + z^T split ----------------
__global__ void prep_all(const float* __restrict__ q, const float* __restrict__ k,
                         const float* __restrict__ v,
                         const float* __restrict__ zq, const float* __restrict__ bq,
                         const float* __restrict__ zk, const float* __restrict__ bk,
                         const float* __restrict__ zv, const float* __restrict__ bv) {
    __shared__ float tsm[32][33];
    if (blockIdx.x < 12) {
        int zi = blockIdx.x >> 2;
        const float* z    = zi == 0 ? zq : (zi == 1 ? zk : zv);
        const float* bias = zi == 0 ? bq : (zi == 1 ? bk : bv);
        int c = (blockIdx.x & 3) * 256 + threadIdx.x;
        float s0 = 0.f, s1 = 0.f, s2 = 0.f, s3 = 0.f;
        #pragma unroll 1
        for (int r = 0; r < EE; r += 4) {
            float t0 = z[(size_t)(r+0) * EE + c];
            float t1 = z[(size_t)(r+1) * EE + c];
            float t2 = z[(size_t)(r+2) * EE + c];
            float t3 = z[(size_t)(r+3) * EE + c];
            s0 = fmaf(t0, t0, s0); s1 = fmaf(t1, t1, s1);
            s2 = fmaf(t2, t2, s2); s3 = fmaf(t3, t3, s3);
        }
        float ss = (s0 + s1) + (s2 + s3);
        float zn = fmaxf(sqrtf(ss), 1e-15f);
        float tcr = 2.f * bias[c];
        float e = expf(tcr), ei = 1.f / e;
        g_zn[zi*EE + c] = zn;
        g_ch[zi*EE + c] = 0.5f * (e + ei) / zn;
        g_sh[zi*EE + c] = 0.5f * (e - ei);
    } else if (blockIdx.x < 12 + 3*512) {
        int idx = blockIdx.x - 12;
        int li = idx / 512;
        const float* x = li == 0 ? q : (li == 1 ? k : v);
        int gw = (idx % 512) * 8 + (threadIdx.x >> 5);
        int lane = threadIdx.x & 31;
        const float4* row = (const float4*)(x + (size_t)gw * EE);
        __nv_bfloat16* xh = g_xh + (size_t)li * MROWS * EE + (size_t)gw * EE;
        __nv_bfloat16* xl = g_xl + (size_t)li * MROWS * EE + (size_t)gw * EE;
        float ss = 0.f;
        #pragma unroll
        for (int i = 0; i < 8; i++) {
            float4 t = row[lane + 32*i];
            ss += t.x*t.x + t.y*t.y + t.z*t.z + t.w*t.w;
            int c0 = (lane + 32*i) * 4;
            __nv_bfloat16 hx = __float2bfloat16(t.x), hy = __float2bfloat16(t.y);
            __nv_bfloat16 hz = __float2bfloat16(t.z), hw = __float2bfloat16(t.w);
            *(__nv_bfloat162*)(xh + c0)     = __nv_bfloat162{hx, hy};
            *(__nv_bfloat162*)(xh + c0 + 2) = __nv_bfloat162{hz, hw};
            *(__nv_bfloat162*)(xl + c0)     = __nv_bfloat162{
                __float2bfloat16(t.x - __bfloat162float(hx)),
                __float2bfloat16(t.y - __bfloat162float(hy))};
            *(__nv_bfloat162*)(xl + c0 + 2) = __nv_bfloat162{
                __float2bfloat16(t.z - __bfloat162float(hz)),
                __float2bfloat16(t.w - __bfloat162float(hw))};
        }
        ss = warp_sum(ss);
        if (lane == 0) g_lamx[li*MROWS + gw] = 2.f / fmaxf(1.f - ss, EPSF);
    } else {
        int idx = blockIdx.x - (12 + 3*512);
        int zi = idx >> 10;
        int t  = idx & 1023;
        int tx = t & 31, ty = t >> 5;
        const float* z = zi == 0 ? zq : (zi == 1 ? zk : zv);
        __nv_bfloat16* zth = g_zth + (size_t)zi * EE * EE;
        __nv_bfloat16* ztl = g_ztl + (size_t)zi * EE * EE;
        int c = threadIdx.x & 31, r0 = threadIdx.x >> 5;
        #pragma unroll
        for (int i = 0; i < 4; i++) {
            int r = r0 + i*8;
            tsm[r][c] = z[(size_t)(ty*32 + r) * EE + tx*32 + c];
        }
        __syncthreads();
        #pragma unroll
        for (int i = 0; i < 4; i++) {
            int r = r0 + i*8;
            float val = tsm[c][r];
            __nv_bfloat16 h = __float2bfloat16(val);
            size_t o = (size_t)(tx*32 + r) * EE + ty*32 + c;
            zth[o] = h;
            ztl[o] = __float2bfloat16(val - __bfloat162float(h));
        }
    }
}

// ---------------- 3xBF16 mma.sync hlinear GEMM (unchanged, verified) ----------------
#define BPIT 40
__global__ void __launch_bounds__(256, 2) hlinear_gemm_tc(int sel) {
    __shared__ __nv_bfloat16 AhS[128*BPIT], AlS[128*BPIT], BhS[128*BPIT], BlS[128*BPIT];
    float* out = pbuf(sel);
    const __nv_bfloat16* xh = g_xh + (size_t)sel * MROWS * EE;
    const __nv_bfloat16* xl = g_xl + (size_t)sel * MROWS * EE;
    const __nv_bfloat16* zh = g_zth + (size_t)sel * EE * EE;
    const __nv_bfloat16* zl = g_ztl + (size_t)sel * EE * EE;
    const float* lamx = g_lamx + sel * MROWS;
    const float* znp  = g_zn + sel * EE;
    const float* chp  = g_ch + sel * EE;
    const float* shp  = g_sh + sel * EE;

    int tid = threadIdx.x;
    int wid = tid >> 5, lane = tid & 31;
    int wm = wid & 1, wn = wid >> 1;
    int row0 = blockIdx.y * 128, col0 = blockIdx.x * 128;
    int lr = lane >> 2, lc = lane & 3;
    int tq = lane >> 3, lr8 = lane & 7;

    uint32_t ahB = (uint32_t)__cvta_generic_to_shared(AhS);
    uint32_t alB = (uint32_t)__cvta_generic_to_shared(AlS);
    uint32_t bhB = (uint32_t)__cvta_generic_to_shared(BhS);
    uint32_t blB = (uint32_t)__cvta_generic_to_shared(BlS);

    float acc[4][4][4];
    #pragma unroll
    for (int mt = 0; mt < 4; mt++)
        #pragma unroll
        for (int nt = 0; nt < 4; nt++)
            #pragma unroll
            for (int i = 0; i < 4; i++) acc[mt][nt][i] = 0.f;

    for (int c = 0; c < 32; c++) {
        if (c) __syncthreads();
        #pragma unroll
        for (int i = 0; i < 2; i++) {
            int idx = i*256 + tid;
            int r = idx >> 2, s2 = idx & 3;
            size_t ga = (size_t)(row0 + r) * EE + c*32 + s2*8;
            size_t gb = (size_t)(col0 + r) * EE + c*32 + s2*8;
            uint32_t so = (uint32_t)(r*80 + s2*16);
            *(int4*)((char*)AhS + so) = *(const int4*)(xh + ga);
            *(int4*)((char*)AlS + so) = *(const int4*)(xl + ga);
            *(int4*)((char*)BhS + so) = *(const int4*)(zh + gb);
            *(int4*)((char*)BlS + so) = *(const int4*)(zl + gb);
        }
        __syncthreads();

        #pragma unroll
        for (int ks = 0; ks < 2; ks++) {
            uint32_t ah[4][4], al[4][4], bh[4][2], bl[4][2];
            #pragma unroll
            for (int mt = 0; mt < 4; mt++) {
                uint32_t ao = (uint32_t)((wm*64 + mt*16 + (tq&1)*8 + lr8)*80 + (2*ks + (tq>>1))*16);
                ldm_x4(ah[mt], ahB + ao);
                ldm_x4(al[mt], alB + ao);
            }
            #pragma unroll
            for (int nt = 0; nt < 4; nt++) {
                uint32_t bo = (uint32_t)((wn*32 + nt*8 + lr8)*80 + (2*ks + (tq&1))*16);
                ldm_x2(bh[nt], bhB + bo);
                ldm_x2(bl[nt], blB + bo);
            }
            #pragma unroll
            for (int mt = 0; mt < 4; mt++)
                #pragma unroll
                for (int nt = 0; nt < 4; nt++) {
                    mma16(acc[mt][nt], ah[mt], bh[nt]);
                    mma16(acc[mt][nt], al[mt], bh[nt]);
                    mma16(acc[mt][nt], ah[mt], bl[nt]);
                }
        }
    }

    #pragma unroll
    for (int mt = 0; mt < 4; mt++) {
        int rA = row0 + wm*64 + mt*16 + lr;
        int rB = rA + 8;
        float lamA = lamx[rA], lamB = lamx[rB];
        float lA1 = lamA - 1.f, lB1 = lamB - 1.f;
        #pragma unroll
        for (int nt = 0; nt < 4; nt++) {
            int cc = col0 + wn*32 + nt*8 + lc*2;
            float zn0 = znp[cc], zn1 = znp[cc+1];
            float ch0 = chp[cc], ch1 = chp[cc+1];
            float sh0 = shp[cc], sh1 = shp[cc+1];
            float a00 = lamA * acc[mt][nt][0] * ch0 - lA1 * sh0;
            float a01 = lamA * acc[mt][nt][1] * ch1 - lA1 * sh1;
            float a10 = lamB * acc[mt][nt][2] * ch0 - lB1 * sh0;
            float a11 = lamB * acc[mt][nt][3] * ch1 - lB1 * sh1;
            float2 oA = make_float2(sinhf(2.f*zn0*asinhf(a00)), sinhf(2.f*zn1*asinhf(a01)));
            float2 oB = make_float2(sinhf(2.f*zn0*asinhf(a10)), sinhf(2.f*zn1*asinhf(a11)));
            *(float2*)&out[(size_t)rA * EE + cc] = oA;
            *(float2*)&out[(size_t)rB * EE + cc] = oB;
        }
    }
}

// ---------------- fused: row normalize + per-head stats + bf16 hi/lo splits ----------------
__global__ void rnkv_fused() {
    int gw = (blockIdx.x * blockDim.x + threadIdx.x) >> 5;
    int lane = threadIdx.x & 31;
    if (gw >= MROWS) return;
    int b = gw >> 10, s = gw & 1023;

    #pragma unroll
    for (int sel = 0; sel <= 2; sel++) {
        float4* row = (float4*)(pbuf(sel) + (size_t)gw * EE);
        __nv_bfloat16* xh = g_xh + (size_t)sel * MROWS * EE + (size_t)gw * EE;
        __nv_bfloat16* xl = g_xl + (size_t)sel * MROWS * EE + (size_t)gw * EE;
        float4 t[8]; float sq[8]; float ss = 0.f;
        #pragma unroll
        for (int i = 0; i < 8; i++) {
            t[i] = row[lane + 32*i];
            sq[i] = t[i].x*t[i].x + t[i].y*t[i].y + t[i].z*t[i].z + t[i].w*t[i].w;
            ss += sq[i];
        }
        ss = warp_sum(ss);
        float f = 1.f / (1.f + sqrtf(1.f + ss));
        float f2 = f * f;
        #pragma unroll
        for (int i = 0; i < 8; i++) {
            t[i].x *= f; t[i].y *= f; t[i].z *= f; t[i].w *= f;
            row[lane + 32*i] = t[i];
            int c0 = (lane + 32*i) * 4;
            __nv_bfloat16 hx = __float2bfloat16(t[i].x), hy = __float2bfloat16(t[i].y);
            __nv_bfloat16 hz = __float2bfloat16(t[i].z), hw = __float2bfloat16(t[i].w);
            *(__nv_bfloat162*)(xh + c0)     = __nv_bfloat162{hx, hy};
            *(__nv_bfloat162*)(xh + c0 + 2) = __nv_bfloat162{hz, hw};
            *(__nv_bfloat162*)(xl + c0)     = __nv_bfloat162{
                __float2bfloat16(t[i].x - __bfloat162float(hx)),
                __float2bfloat16(t[i].y - __bfloat162float(hy))};
            *(__nv_bfloat162*)(xl + c0 + 2) = __nv_bfloat162{
                __float2bfloat16(t[i].z - __bfloat162float(hz)),
                __float2bfloat16(t[i].w - __bfloat162float(hw))};
            float hs = sq[i] * f2;
            #pragma unroll
            for (int o = 8; o > 0; o >>= 1) hs += __shfl_xor_sync(0xffffffffu, hs, o);
            if ((lane & 15) == 0) {
                int h = 2*i + (lane >> 4);
                int idx = ((b*HH + h) * SS) + s;
                if (sel == 0) {
                    g_q2[idx] = hs;
                    g_iomq[idx] = 1.f / fmaxf(1.f - hs, EPSF);
                } else if (sel == 1) {
                    g_k2[idx] = hs;
                    g_ik2[idx] = 1.f / fmaxf(1.f - hs, EPSF);
                } else {
                    g_lamv[idx] = 2.f / fmaxf(1.f - hs, EPSF);
                }
            }
        }
    }
}

// ---------------- attention: 64q x 64k flash tile via 3xBF16 mma.sync ----------------
#define AROW 144
#define ATT_SMEM 57088
#define REDP 66
__global__ void __launch_bounds__(256) attention_kernel(float scale_cat) {
    extern __shared__ char smraw[];
    float* mxex = (float*)(smraw + 55296);
    float* adex = (float*)(smraw + 55808);
    float* kst  = (float*)(smraw + 56320);
    float* red  = (float*)(smraw + 18432);
    uint32_t sb  = (uint32_t)__cvta_generic_to_shared(smraw);
    uint32_t qhB = sb, qlB = sb + 9216, khB = sb + 18432, klB = sb + 27648;
    uint32_t vhB = sb + 36864, vlB = sb + 46080;

    int tid = threadIdx.x;
    int lane = tid & 31;
    int w = tid >> 5;
    int qw = w & 3, khalf = w >> 2;
    int tq = lane >> 3, lr8 = lane & 7;
    int bh = blockIdx.x;
    int b = bh >> 4, h = bh & 15;
    int q0 = blockIdx.y * 64;

    const __nv_bfloat16* qhg = g_xh + (size_t)(b*SS + q0) * EE + h*DD;
    const __nv_bfloat16* qlg = g_xl + (size_t)(b*SS + q0) * EE + h*DD;
    const __nv_bfloat16* khg = g_xh + (size_t)MROWS*EE   + (size_t)(b*SS) * EE + h*DD;
    const __nv_bfloat16* klg = g_xl + (size_t)MROWS*EE   + (size_t)(b*SS) * EE + h*DD;
    const __nv_bfloat16* vhg = g_xh + (size_t)2*MROWS*EE + (size_t)(b*SS) * EE + h*DD;
    const __nv_bfloat16* vlg = g_xl + (size_t)2*MROWS*EE + (size_t)(b*SS) * EE + h*DD;

    #pragma unroll
    for (int i = 0; i < 2; i++) {
        int idx = i*256 + tid;
        int r = idx >> 3, s2 = idx & 7;
        size_t go = (size_t)r * EE + s2*8;
        uint32_t so = (uint32_t)(r*AROW + s2*16);
        *(int4*)(smraw + so)        = *(const int4*)(qhg + go);
        *(int4*)(smraw + 9216 + so) = *(const int4*)(qlg + go);
    }

    int rloc = lane >> 2;
    int qrow = qw*16 + rloc;
    float q2v[2], cqv[2];
    #pragma unroll
    for (int j = 0; j < 2; j++) {
        int qi = bh*SS + q0 + qrow + j*8;
        q2v[j] = g_q2[qi];
        cqv[j] = 2.f * g_iomq[qi];
    }

    float O[8][4];
    #pragma unroll
    for (int nd = 0; nd < 8; nd++)
        #pragma unroll
        for (int i = 0; i < 4; i++) O[nd][i] = 0.f;
    float Rm[2] = {0.f, 0.f}, adp[2] = {0.f, 0.f};

    for (int kt = 0; kt < SS; kt += 64) {
        __syncthreads();
        #pragma unroll
        for (int i = 0; i < 2; i++) {
            int idx = i*256 + tid;
            int r = idx >> 3, s2 = idx & 7;
            size_t go = (size_t)(kt + r) * EE + s2*8;
            uint32_t so = (uint32_t)(r*AROW + s2*16);
            *(int4*)(smraw + 18432 + so) = *(const int4*)(khg + go);
            *(int4*)(smraw + 27648 + so) = *(const int4*)(klg + go);
            *(int4*)(smraw + 36864 + so) = *(const int4*)(vhg + go);
            *(int4*)(smraw + 46080 + so) = *(const int4*)(vlg + go);
        }
        if (tid < 64) {
            kst[tid]       = g_k2[bh*SS + kt + tid];
            kst[64 + tid]  = g_ik2[bh*SS + kt + tid];
            kst[128 + tid] = g_lamv[bh*SS + kt + tid];
        }
        __syncthreads();

        // QK
        float S[4][4];
        #pragma unroll
        for (int nt = 0; nt < 4; nt++)
            #pragma unroll
            for (int i = 0; i < 4; i++) S[nt][i] = 0.f;
        #pragma unroll
        for (int ks = 0; ks < 4; ks++) {
            uint32_t ah[4], al[4];
            uint32_t ao = (uint32_t)((qw*16 + (tq&1)*8 + lr8)*AROW + (2*ks + (tq>>1))*16);
            ldm_x4(ah, qhB + ao);
            ldm_x4(al, qlB + ao);
            #pragma unroll
            for (int nt = 0; nt < 4; nt++) {
                uint32_t bhf[2], blf[2];
                uint32_t bo = (uint32_t)((khalf*32 + nt*8 + lr8)*AROW + (2*ks + (tq&1))*16);
                ldm_x2(bhf, khB + bo);
                ldm_x2(blf, klB + bo);
                mma16(S[nt], ah, bhf);
                mma16(S[nt], al, bhf);
                mma16(S[nt], ah, blf);
            }
        }

        // score transform -> R, local row max
        float lmx[2] = {0.f, 0.f};
        #pragma unroll
        for (int nt = 0; nt < 4; nt++) {
            int kl0 = khalf*32 + nt*8 + 2*(lane & 3);
            float k2a = kst[kl0],     cka = kst[64 + kl0];
            float k2b = kst[kl0 + 1], ckb = kst[64 + kl0 + 1];
            #pragma unroll
            for (int e = 0; e < 4; e++) {
                int j = e >> 1;
                float k2i = (e & 1) ? k2b : k2a;
                float cki = (e & 1) ? ckb : cka;
                float d2 = fmaxf(q2v[j] + k2i - 2.f*S[nt][e], 0.f);
                float x  = fmaxf(d2 * cki * cqv[j], 1e-6f);
                float r  = fmaxf(1.f + x - sqrtf(x*(x + 2.f)), 0.f);
                S[nt][e] = r;
                lmx[j] = fmaxf(lmx[j], r);
            }
        }
        #pragma unroll
        for (int j = 0; j < 2; j++) {
            lmx[j] = fmaxf(lmx[j], __shfl_xor_sync(0xffffffffu, lmx[j], 1));
            lmx[j] = fmaxf(lmx[j], __shfl_xor_sync(0xffffffffu, lmx[j], 2));
        }
        if ((lane & 3) == 0) {
            mxex[khalf*64 + qrow]     = lmx[0];
            mxex[khalf*64 + qrow + 8] = lmx[1];
        }
        __syncthreads();
        float inv[2], rs[2];
        #pragma unroll
        for (int j = 0; j < 2; j++) {
            int rr = qrow + j*8;
            float cmb = fmaxf(Rm[j], fmaxf(mxex[rr], mxex[64 + rr]));
            rs[j] = (Rm[j] > 0.f) ? (Rm[j] / cmb) : 0.f;
            Rm[j] = cmb;
            inv[j] = 1.f / cmb;
            adp[j] *= rs[j];
        }
        #pragma unroll
        for (int nd = 0; nd < 8; nd++) {
            O[nd][0] *= rs[0]; O[nd][1] *= rs[0];
            O[nd][2] *= rs[1]; O[nd][3] *= rs[1];
        }

        // P frags: fold lambda_k into P (THE FIX), aden uses p*(lambda-1)
        #pragma unroll
        for (int ks2 = 0; ks2 < 2; ks2++) {
            uint32_t pah[4], pal[4];
            #pragma unroll
            for (int half = 0; half < 2; half++) {
                int nt = 2*ks2 + half;
                int kl0 = khalf*32 + nt*8 + 2*(lane & 3);
                float lma = kst[128 + kl0];
                float lmb = kst[128 + kl0 + 1];
                float p0 = S[nt][0] * inv[0], p1 = S[nt][1] * inv[0];
                float p2 = S[nt][2] * inv[1], p3 = S[nt][3] * inv[1];
                adp[0] += p0*(lma - 1.f) + p1*(lmb - 1.f);
                adp[1] += p2*(lma - 1.f) + p3*(lmb - 1.f);
                float w0 = p0 * lma, w1 = p1 * lmb;
                float w2 = p2 * lma, w3 = p3 * lmb;
                float h0 = tobf(w0), h1 = tobf(w1), h2 = tobf(w2), h3 = tobf(w3);
                pah[half*2 + 0] = packbf(h0, h1);
                pah[half*2 + 1] = packbf(h2, h3);
                pal[half*2 + 0] = packbf(w0 - h0, w1 - h1);
                pal[half*2 + 1] = packbf(w2 - h2, w3 - h3);
            }
            #pragma unroll
            for (int nd = 0; nd < 8; nd++) {
                uint32_t bhf[2], blf[2];
                uint32_t vo = (uint32_t)((khalf*32 + ks2*16 + (lane & 15))*AROW + nd*16);
                ldm_x2t(bhf, vhB + vo);
                ldm_x2t(blf, vlB + vo);
                mma16(O[nd], pah, bhf);
                mma16(O[nd], pal, bhf);
                mma16(O[nd], pah, blf);
            }
        }
    }
    __syncthreads();

    // cross-half reduction
    int dbase = 2*(lane & 3);
    if (khalf == 1) {
        #pragma unroll
        for (int nd = 0; nd < 8; nd++) {
            int d = nd*8 + dbase;
            *(float2*)&red[(qw*16 + rloc)*REDP + d]     = make_float2(O[nd][0], O[nd][1]);
            *(float2*)&red[(qw*16 + rloc + 8)*REDP + d] = make_float2(O[nd][2], O[nd][3]);
        }
        #pragma unroll
        for (int j = 0; j < 2; j++) {
            float a = adp[j];
            a += __shfl_xor_sync(0xffffffffu, a, 1);
            a += __shfl_xor_sync(0xffffffffu, a, 2);
            if ((lane & 3) == 0) adex[qw*16 + rloc + j*8] = a;
        }
    }
    __syncthreads();
    if (khalf == 0) {
        float adt[2];
        #pragma unroll
        for (int j = 0; j < 2; j++) {
            float a = adp[j];
            a += __shfl_xor_sync(0xffffffffu, a, 1);
            a += __shfl_xor_sync(0xffffffffu, a, 2);
            adt[j] = a + adex[qw*16 + rloc + j*8];
        }
        #pragma unroll
        for (int nd = 0; nd < 8; nd++) {
            int d = nd*8 + dbase;
            float2 r0 = *(const float2*)&red[(qw*16 + rloc)*REDP + d];
            float2 r1 = *(const float2*)&red[(qw*16 + rloc + 8)*REDP + d];
            O[nd][0] += r0.x; O[nd][1] += r0.y;
            O[nd][2] += r1.x; O[nd][3] += r1.y;
        }
        float iad[2], usq[2];
        #pragma unroll
        for (int j = 0; j < 2; j++) iad[j] = 1.f / fmaxf(adt[j], EPSF);
        usq[0] = 0.f; usq[1] = 0.f;
        #pragma unroll
        for (int nd = 0; nd < 8; nd++) {
            float u0 = O[nd][0]*iad[0], u1 = O[nd][1]*iad[0];
            float u2 = O[nd][2]*iad[1], u3 = O[nd][3]*iad[1];
            O[nd][0] = u0; O[nd][1] = u1; O[nd][2] = u2; O[nd][3] = u3;
            usq[0] += u0*u0 + u1*u1;
            usq[1] += u2*u2 + u3*u3;
        }
        #pragma unroll
        for (int j = 0; j < 2; j++) {
            usq[j] += __shfl_xor_sync(0xffffffffu, usq[j], 1);
            usq[j] += __shfl_xor_sync(0xffffffffu, usq[j], 2);
        }
        float fj[2];
        #pragma unroll
        for (int j = 0; j < 2; j++) {
            float t = 1.f / (1.f + sqrtf(fmaxf(1.f - usq[j], EPSF)));
            float msq = usq[j] * t * t;
            float n = sqrtf(fmaxf(msq, 1e-15f));
            float tc = fminf(n, 1.f - 1e-6f);
            float ath = 0.5f * logf((1.f + tc) / (1.f - tc));
            fj[j] = ath / n * scale_cat * t;
        }
        #pragma unroll
        for (int j = 0; j < 2; j++) {
            size_t go = (size_t)(b*SS + q0 + qrow + j*8) * EE + h*DD;
            #pragma unroll
            for (int nd = 0; nd < 8; nd++) {
                int d = nd*8 + dbase;
                *(float2*)&g_tv[go + d] = make_float2(O[nd][j*2]*fj[j], O[nd][j*2+1]*fj[j]);
            }
        }
    }
}

// ---------------- final expmap0 over full E rows ----------------
__global__ void expmap_out(float* __restrict__ out) {
    int row = blockIdx.x;
    const float4* tv = (const float4*)(g_tv + (size_t)row * EE);
    __shared__ float red[8];
    __shared__ float stot;
    float4 v = tv[threadIdx.x];
    float ss = v.x*v.x + v.y*v.y + v.z*v.z + v.w*v.w;
    ss = warp_sum(ss);
    int lane = threadIdx.x & 31, wid = threadIdx.x >> 5;
    if (lane == 0) red[wid] = ss;
    __syncthreads();
    if (threadIdx.x == 0) {
        float t = 0.f;
        #pragma unroll
        for (int i = 0; i < 8; i++) t += red[i];
        stot = t;
    }
    __syncthreads();
    float n = sqrtf(fmaxf(stot, 1e-15f));
    float f = tanhf(n) / n;
    v.x *= f; v.y *= f; v.z *= f; v.w *= f;
    ((float4*)out)[(size_t)row * 256 + threadIdx.x] = v;
}

// ---------------- launch ----------------
extern "C" void kernel_launch(void* const* d_in, const int* in_sizes, int n_in,
                              void* d_out, int out_size) {
    const float* q  = (const float*)d_in[0];
    const float* k  = (const float*)d_in[1];
    const float* v  = (const float*)d_in[2];
    const float* zq = (const float*)d_in[3];
    const float* bq = (const float*)d_in[4];
    const float* zk = (const float*)d_in[5];
    const float* bk = (const float*)d_in[6];
    const float* zv = (const float*)d_in[7];
    const float* bv = (const float*)d_in[8];
    float* out = (float*)d_out;

    double b1 = lgamma(EE/2.0) + lgamma(0.5) - lgamma(EE/2.0 + 0.5);
    double b2 = lgamma(DD/2.0) + lgamma(0.5) - lgamma(DD/2.0 + 0.5);
    float scale_cat = (float)exp(b1 - b2);

    cudaFuncSetAttribute(attention_kernel, cudaFuncAttributeMaxDynamicSharedMemorySize, ATT_SMEM);

    prep_all<<<12 + 3*512 + 3*1024, 256>>>(q, k, v, zq, bq, zk, bk, zv, bv);  // launch 0

    dim3 gg(EE/128, MROWS/128);
    hlinear_gemm_tc<<<gg, 256>>>(0);                                          // launch 1
    hlinear_gemm_tc<<<gg, 256>>>(1);                                          // launch 2
    hlinear_gemm_tc<<<gg, 256>>>(2);                                          // launch 3

    rnkv_fused<<<MROWS/8, 256>>>();                                           // launch 4

    dim3 ga(BB*HH, SS/64);
    attention_kernel<<<ga, 256, ATT_SMEM>>>(scale_cat);                       // launch 5

    expmap_out<<<MROWS, 256>>>(out);                                          // launch 6
}